// round 3
// baseline (speedup 1.0000x reference)
#include <cuda_runtime.h>
#include <math.h>
#include <stdint.h>

#define BB 8
#define SS 512
#define NSPAN 512
#define H 768
#define NH 4
#define HD 192
#define FFN_DIM 3072
#define LSPAN 32
#define BS (BB*SS)      // 4096 token rows
#define BN (BB*NSPAN)   // 4096 span rows

typedef unsigned long long ull;

// ---------------- scratch (static device globals; no allocations) ----------
__device__ float g_X[BS*H];
__device__ float g_KV[(size_t)BS*2*H];   // K cols 0..767, V cols 768..1535
__device__ float g_qc[H];
__device__ float g_bias2[H];             // out_b + dummy_query
__device__ float g_ctx[(size_t)BN*H];
__device__ float g_ao[(size_t)BN*H];
__device__ float g_y[(size_t)BN*H];
__device__ float g_h1[(size_t)BN*FFN_DIM];
__device__ float g_ff[(size_t)BN*H];

// packed fp32x2 FMA (sm_100+): d = a*b + c elementwise on two lanes
__device__ __forceinline__ ull ffma2(ull a, ull b, ull c) {
    ull d;
    asm("fma.rn.f32x2 %0, %1, %2, %3;" : "=l"(d) : "l"(a), "l"(b), "l"(c));
    return d;
}
__device__ __forceinline__ ull dup2(float x) {
    unsigned u = __float_as_uint(x);
    return (ull)u | ((ull)u << 32);
}

// ---------------- kernel 1: X = token_reps + sinusoidal PE -----------------
__global__ void add_pe_kernel(const float* __restrict__ tok) {
    int idx = blockIdx.x * blockDim.x + threadIdx.x;
    if (idx >= BS * H) return;
    int d   = idx % H;
    int row = idx / H;
    int pos = row % SS;
    int i2  = d & ~1;
    const float c = (float)(-9.210340371976184 / (double)H); // -ln(10000)/H
    float freq = expf((float)i2 * c);
    float ang  = (float)pos * freq;
    float pe   = (d & 1) ? cosf(ang) : sinf(ang);
    g_X[idx] = tok[idx] + pe;
}

// ---------------- kernel 2: q projection + fused bias ----------------------
__global__ void proj_q_kernel(const float* __restrict__ dq,
                              const float* __restrict__ in_w,
                              const float* __restrict__ in_b,
                              const float* __restrict__ out_b) {
    int o = blockIdx.x * blockDim.x + threadIdx.x;
    if (o >= H) return;
    const float* wr = in_w + (size_t)o * H;
    float acc = in_b[o];
    #pragma unroll 4
    for (int c = 0; c < H; c++) acc += dq[c] * wr[c];
    g_qc[o]    = acc;
    g_bias2[o] = out_b[o] + dq[o];
}

// ---------------- tiled SGEMM via FFMA2: C[M,N]=A[M,K]@W[N,K]^T + bias -----
// BM=128, BN=64, BK=16, 256 threads. Per-thread 8x4 outputs as 4x4 f32x2
// pairs (paired along M). B tile stored DUPLICATED in smem so both FFMA2
// operands are straight 8B shared loads.
template<bool RELU>
__global__ void sgemm_nt(const float* __restrict__ A, const float* __restrict__ W,
                         const float* __restrict__ bias, float* __restrict__ C,
                         int M, int N, int K) {
    __shared__ float As[16][128];    // [k][m]
    __shared__ float Bsd[16][128];   // [k][2*c(+1)] duplicated pairs, 64 cols
    int tid = threadIdx.x;
    int m0  = blockIdx.y * 128;
    int n0  = blockIdx.x * 64;
    int tx  = tid & 15;    // 4 output cols: n0 + tx*4 ..
    int ty  = tid >> 4;    // 8 output rows: m0 + ty*8 ..

    ull acc[4][4];
    #pragma unroll
    for (int p = 0; p < 4; p++)
        #pragma unroll
        for (int j = 0; j < 4; j++) acc[p][j] = 0ull;

    for (int k0 = 0; k0 < K; k0 += 16) {
        // load A tile (transposed into [k][m])
        #pragma unroll
        for (int r = 0; r < 2; r++) {
            int lin = tid + r * 256;
            int row = lin >> 2;           // 0..127
            int cv  = (lin & 3) << 2;     // 0,4,8,12
            float4 v = *reinterpret_cast<const float4*>(&A[(size_t)(m0 + row) * K + k0 + cv]);
            As[cv + 0][row] = v.x; As[cv + 1][row] = v.y;
            As[cv + 2][row] = v.z; As[cv + 3][row] = v.w;
        }
        // load W tile, store duplicated: Bsd[k][2c]=Bsd[k][2c+1]=w
        {
            int row = tid >> 2;           // 0..63 = output col
            int cv  = (tid & 3) << 2;     // k offset
            float4 v = *reinterpret_cast<const float4*>(&W[(size_t)(n0 + row) * K + k0 + cv]);
            *reinterpret_cast<ull*>(&Bsd[cv + 0][2 * row]) = dup2(v.x);
            *reinterpret_cast<ull*>(&Bsd[cv + 1][2 * row]) = dup2(v.y);
            *reinterpret_cast<ull*>(&Bsd[cv + 2][2 * row]) = dup2(v.z);
            *reinterpret_cast<ull*>(&Bsd[cv + 3][2 * row]) = dup2(v.w);
        }
        __syncthreads();
        #pragma unroll
        for (int kk = 0; kk < 16; kk++) {
            // a-pairs: rows (ty*8+2p, ty*8+2p+1) — adjacent in As[kk]
            ulonglong2 a01 = *reinterpret_cast<const ulonglong2*>(&As[kk][ty * 8]);
            ulonglong2 a23 = *reinterpret_cast<const ulonglong2*>(&As[kk][ty * 8 + 4]);
            // b duplicated pairs for cols tx*4 .. tx*4+3
            ulonglong2 b01 = *reinterpret_cast<const ulonglong2*>(&Bsd[kk][tx * 8]);
            ulonglong2 b23 = *reinterpret_cast<const ulonglong2*>(&Bsd[kk][tx * 8 + 4]);
            ull ap[4] = {a01.x, a01.y, a23.x, a23.y};
            ull bp[4] = {b01.x, b01.y, b23.x, b23.y};
            #pragma unroll
            for (int p = 0; p < 4; p++)
                #pragma unroll
                for (int j = 0; j < 4; j++)
                    acc[p][j] = ffma2(ap[p], bp[j], acc[p][j]);
        }
        __syncthreads();
    }

    #pragma unroll
    for (int p = 0; p < 4; p++) {
        int mrow = m0 + ty * 8 + 2 * p;
        #pragma unroll
        for (int j = 0; j < 4; j++) {
            int ncol = n0 + tx * 4 + j;
            float2 f = *reinterpret_cast<float2*>(&acc[p][j]);
            float b = bias[ncol];
            float v0 = f.x + b, v1 = f.y + b;
            if (RELU) { v0 = fmaxf(v0, 0.f); v1 = fmaxf(v1, 0.f); }
            C[(size_t)mrow * N + ncol]       = v0;
            C[(size_t)(mrow + 1) * N + ncol] = v1;
        }
    }
}

// ---------------- attention: 1 block per span, warp per head ---------------
__global__ void attn_kernel(const int* __restrict__ span_ids,
                            const int* __restrict__ masks) {
    int span = blockIdx.x;
    int b    = span / NSPAN;
    __shared__ float sq[H];
    __shared__ float sattn[NH][LSPAN];
    __shared__ int sh_start, sh_len;

    int tid = threadIdx.x;           // 128
    if (tid == 0) {
        int st = span_ids[span * 2 + 0];
        int en = span_ids[span * 2 + 1];
        int mk = masks[span] ? 1 : 0;
        sh_start = st;
        sh_len   = (en - st) * mk;
    }
    for (int i = tid; i < H; i += 128) sq[i] = g_qc[i];
    __syncthreads();

    int start = sh_start, len = sh_len;
    int h = tid >> 5;
    int l = tid & 31;

    const float scale = 1.0f / sqrtf((float)HD);
    float score = -INFINITY;
    if (l < len) {
        const float* kr = g_KV + ((size_t)(b * SS + start + l)) * (2 * H) + h * HD;
        const float* qh = sq + h * HD;
        float acc = 0.f;
        #pragma unroll
        for (int d = 0; d < HD; d += 4) {
            float4 k4 = *reinterpret_cast<const float4*>(kr + d);
            acc += qh[d] * k4.x + qh[d + 1] * k4.y + qh[d + 2] * k4.z + qh[d + 3] * k4.w;
        }
        score = acc * scale;
    }
    float mx = score;
    #pragma unroll
    for (int o = 16; o > 0; o >>= 1) mx = fmaxf(mx, __shfl_xor_sync(0xffffffffu, mx, o));
    float e = (l < len) ? expf(score - mx) : 0.f;
    float sum = e;
    #pragma unroll
    for (int o = 16; o > 0; o >>= 1) sum += __shfl_xor_sync(0xffffffffu, sum, o);
    sattn[h][l] = (sum > 0.f) ? (e / sum) : 0.f;
    __syncthreads();

    const float* rowbase = g_KV + ((size_t)(b * SS + start)) * (2 * H) + H;
    for (int o = tid; o < H; o += 128) {
        int hh = o / HD;
        float acc = 0.f;
        const float* vp = rowbase + o;
        for (int l2 = 0; l2 < len; l2++)
            acc += sattn[hh][l2] * vp[(size_t)l2 * 2 * H];
        g_ctx[(size_t)span * H + o] = acc;
    }
}

// ---------------- LayerNorm (block per row), optional residual + mask ------
__global__ void ln_kernel(const float* __restrict__ in, const float* __restrict__ res,
                          const float* __restrict__ gam, const float* __restrict__ bet,
                          float* __restrict__ out, const int* __restrict__ masks,
                          int has_res, int mask_out) {
    int row = blockIdx.x;
    __shared__ float sv[H];
    __shared__ float red[8];
    int tid = threadIdx.x;           // 256

    float s = 0.f;
    for (int i = tid; i < H; i += 256) {
        float v = in[(size_t)row * H + i];
        if (has_res) v += res[(size_t)row * H + i];
        sv[i] = v;
        s += v;
    }
    #pragma unroll
    for (int o = 16; o > 0; o >>= 1) s += __shfl_xor_sync(0xffffffffu, s, o);
    if ((tid & 31) == 0) red[tid >> 5] = s;
    __syncthreads();
    float tot = 0.f;
    #pragma unroll
    for (int w = 0; w < 8; w++) tot += red[w];
    float mean = tot / (float)H;
    __syncthreads();

    float vs = 0.f;
    for (int i = tid; i < H; i += 256) {
        float d = sv[i] - mean;
        vs += d * d;
    }
    #pragma unroll
    for (int o = 16; o > 0; o >>= 1) vs += __shfl_xor_sync(0xffffffffu, vs, o);
    if ((tid & 31) == 0) red[tid >> 5] = vs;
    __syncthreads();
    float vtot = 0.f;
    #pragma unroll
    for (int w = 0; w < 8; w++) vtot += red[w];
    float rstd = rsqrtf(vtot / (float)H + 1e-5f);

    int keep = mask_out ? (masks[row] ? 1 : 0) : 1;
    for (int i = tid; i < H; i += 256) {
        float val = (sv[i] - mean) * rstd * gam[i] + bet[i];
        out[(size_t)row * H + i] = keep ? val : 0.f;
    }
}

// ---------------- launch ---------------------------------------------------
extern "C" void kernel_launch(void* const* d_in, const int* in_sizes, int n_in,
                              void* d_out, int out_size) {
    const float* tok   = (const float*)d_in[0];
    const int*   sids  = (const int*)d_in[1];
    const int*   masks = (const int*)d_in[2];    // bool -> int32 on the wire
    int base = (n_in >= 15) ? 4 : 3;
    const float* dq    = (const float*)d_in[base + 0];
    const float* in_w  = (const float*)d_in[base + 1];
    const float* in_b  = (const float*)d_in[base + 2];
    const float* out_w = (const float*)d_in[base + 3];
    const float* out_b = (const float*)d_in[base + 4];
    const float* ln_g  = (const float*)d_in[base + 5];
    const float* ln_b  = (const float*)d_in[base + 6];
    const float* w1    = (const float*)d_in[base + 7];
    const float* b1    = (const float*)d_in[base + 8];
    const float* w2    = (const float*)d_in[base + 9];
    const float* b2    = (const float*)d_in[base + 10];
    float* outp = (float*)d_out;

    float *pX, *pKV, *pCtx, *pAo, *pY, *pH1, *pFf, *pQc, *pBias2;
    cudaGetSymbolAddress((void**)&pX,     g_X);
    cudaGetSymbolAddress((void**)&pKV,    g_KV);
    cudaGetSymbolAddress((void**)&pCtx,   g_ctx);
    cudaGetSymbolAddress((void**)&pAo,    g_ao);
    cudaGetSymbolAddress((void**)&pY,     g_y);
    cudaGetSymbolAddress((void**)&pH1,    g_h1);
    cudaGetSymbolAddress((void**)&pFf,    g_ff);
    cudaGetSymbolAddress((void**)&pQc,    g_qc);
    cudaGetSymbolAddress((void**)&pBias2, g_bias2);

    add_pe_kernel<<<(BS * H + 255) / 256, 256>>>(tok);
    proj_q_kernel<<<3, 256>>>(dq, in_w, in_b, out_b);
    sgemm_nt<false><<<dim3(1536 / 64, BS / 128), 256>>>(
        pX, in_w + (size_t)H * H, in_b + H, pKV, BS, 2 * H, H);
    attn_kernel<<<BN, 128>>>(sids, masks);
    sgemm_nt<false><<<dim3(H / 64, BN / 128), 256>>>(
        pCtx, out_w, pBias2, pAo, BN, H, H);
    ln_kernel<<<BN, 256>>>(pAo, nullptr, ln_g, ln_b, pY, nullptr, 0, 0);
    sgemm_nt<true><<<dim3(FFN_DIM / 64, BN / 128), 256>>>(
        pY, w1, b1, pH1, BN, FFN_DIM, H);
    sgemm_nt<false><<<dim3(H / 64, BN / 128), 256>>>(
        pH1, w2, b2, pFf, BN, H, FFN_DIM);
    ln_kernel<<<BN, 256>>>(pFf, pY, ln_g, ln_b, outp, masks, 1, 1);
    (void)in_sizes; (void)out_size;
}

// round 5
// speedup vs baseline: 2.9038x; 2.9038x over previous
#include <cuda_runtime.h>
#include <cuda_bf16.h>
#include <math.h>
#include <stdint.h>

#define BB 8
#define SS 512
#define NSPAN 512
#define H 768
#define NH 4
#define HD 192
#define FFN_DIM 3072
#define LSPAN 32
#define BS (BB*SS)      // 4096 token rows
#define BN (BB*NSPAN)   // 4096 span rows

typedef __nv_bfloat16 bf16;

// ---------------- scratch (static device globals; no allocations) ----------
__device__ bf16  g_Xh[(size_t)BS*H], g_Xl[(size_t)BS*H];
__device__ bf16  g_kvwh[(size_t)2*H*H], g_kvwl[(size_t)2*H*H];
__device__ bf16  g_owh[(size_t)H*H],   g_owl[(size_t)H*H];
__device__ bf16  g_w1h[(size_t)FFN_DIM*H], g_w1l[(size_t)FFN_DIM*H];
__device__ bf16  g_w2h[(size_t)H*FFN_DIM], g_w2l[(size_t)H*FFN_DIM];
__device__ float g_KV[(size_t)BS*2*H];   // K cols 0..767, V cols 768..1535 (fp32)
__device__ bf16  g_ctxh[(size_t)BN*H], g_ctxl[(size_t)BN*H];
__device__ float g_ao[(size_t)BN*H];
__device__ float g_y[(size_t)BN*H];
__device__ bf16  g_yh[(size_t)BN*H], g_yl[(size_t)BN*H];
__device__ bf16  g_h1h[(size_t)BN*FFN_DIM], g_h1l[(size_t)BN*FFN_DIM];
__device__ float g_ff[(size_t)BN*H];
__device__ float g_qc[H];
__device__ float g_bias2[H];             // out_b + dummy_query

// ---------------- PTX helpers ----------------------------------------------
__device__ __forceinline__ uint32_t smem_u32(const void* p) {
    uint32_t a;
    asm("{ .reg .u64 t; cvta.to.shared.u64 t, %1; cvt.u32.u64 %0, t; }" : "=r"(a) : "l"(p));
    return a;
}
#define LDSM4(r, addr) \
    asm volatile("ldmatrix.sync.aligned.m8n8.x4.shared.b16 {%0,%1,%2,%3}, [%4];" \
        : "=r"((r)[0]), "=r"((r)[1]), "=r"((r)[2]), "=r"((r)[3]) : "r"(addr))
#define MMA_BF16(d, a, b0, b1) \
    asm volatile("mma.sync.aligned.m16n8k16.row.col.f32.bf16.bf16.f32 " \
        "{%0,%1,%2,%3}, {%4,%5,%6,%7}, {%8,%9}, {%0,%1,%2,%3};" \
        : "+f"((d)[0]), "+f"((d)[1]), "+f"((d)[2]), "+f"((d)[3]) \
        : "r"((a)[0]), "r"((a)[1]), "r"((a)[2]), "r"((a)[3]), "r"(b0), "r"(b1))

#define TSTRIDE 72                       // bf16 elems per smem row (64 + 8 pad)
#define TILE_B (128*TSTRIDE*2)           // 18432 B per tile
#define SMEM_TOTAL (4*TILE_B + 512)      // Ah, Al, Wh, Wl + bias

// ---------------- HMMA GEMM: C[M,N] = (Ah+Al)[M,K] @ (Wh+Wl)[N,K]^T + bias
// 3-term bf16 split. Block 128x128, 256 thr (8 warps, 4Mx2N), warp 32x64.
// MODE 0: fp32 out. MODE 1: relu then bf16 hi/lo pair out.
template<int MODE>
__global__ void __launch_bounds__(256, 1)
hmma_gemm(const bf16* __restrict__ Ah, const bf16* __restrict__ Al,
          const bf16* __restrict__ Wh, const bf16* __restrict__ Wl,
          const float* __restrict__ bias, float* __restrict__ C,
          bf16* __restrict__ Ch, bf16* __restrict__ Cl, int N, int K) {
    extern __shared__ char sm[];
    uint32_t sb = smem_u32(sm);
    float* sbias = (float*)(sm + 4 * TILE_B);
    int tid = threadIdx.x, wid = tid >> 5, lid = tid & 31;
    int m0 = blockIdx.y * 128, n0 = blockIdx.x * 128;
    int warp_m = wid >> 1, warp_n = wid & 1;     // 4 x 2
    int wm0 = warp_m * 32, wn0 = warp_n * 64;

    if (tid < 128) sbias[tid] = bias[n0 + tid];

    float acc[2][8][4];
    #pragma unroll
    for (int mt = 0; mt < 2; mt++)
        #pragma unroll
        for (int nt = 0; nt < 8; nt++)
            #pragma unroll
            for (int j = 0; j < 4; j++) acc[mt][nt][j] = 0.f;

    // per-thread ldmatrix base offsets (bytes)
    uint32_t a_off = sb + (uint32_t)(((wm0 + (lid & 15)) * TSTRIDE + ((lid >> 4) << 3)) * 2);
    uint32_t w_off = sb + 2 * TILE_B +
                     (uint32_t)(((wn0 + (lid & 15)) * TSTRIDE + ((lid >> 4) << 3)) * 2);

    for (int k0 = 0; k0 < K; k0 += 64) {
        // ---- load 4 tiles (128 rows x 64 bf16 each) ----
        #pragma unroll
        for (int it = 0; it < 4; it++) {
            int lin = tid + it * 256;            // 1024 16B chunks per tile
            int row = lin >> 3, c16 = lin & 7;
            uint32_t so = (uint32_t)(row * TSTRIDE * 2 + c16 * 16);
            const uint4* pa = reinterpret_cast<const uint4*>(Ah + (size_t)(m0 + row) * K + k0) + c16;
            const uint4* pl = reinterpret_cast<const uint4*>(Al + (size_t)(m0 + row) * K + k0) + c16;
            const uint4* pb = reinterpret_cast<const uint4*>(Wh + (size_t)(n0 + row) * K + k0) + c16;
            const uint4* pc = reinterpret_cast<const uint4*>(Wl + (size_t)(n0 + row) * K + k0) + c16;
            *reinterpret_cast<uint4*>(sm + 0 * TILE_B + so) = *pa;
            *reinterpret_cast<uint4*>(sm + 1 * TILE_B + so) = *pl;
            *reinterpret_cast<uint4*>(sm + 2 * TILE_B + so) = *pb;
            *reinterpret_cast<uint4*>(sm + 3 * TILE_B + so) = *pc;
        }
        __syncthreads();

        #pragma unroll
        for (int kk = 0; kk < 4; kk++) {
            uint32_t ah[2][4], al2[2][4], bh[4][4], bl[4][4];
            #pragma unroll
            for (int t = 0; t < 2; t++) {
                uint32_t off = (uint32_t)(t * 16 * TSTRIDE * 2 + kk * 32);
                LDSM4(ah[t],  a_off + off);
                LDSM4(al2[t], a_off + TILE_B + off);
            }
            #pragma unroll
            for (int g = 0; g < 4; g++) {
                uint32_t off = (uint32_t)(g * 16 * TSTRIDE * 2 + kk * 32);
                LDSM4(bh[g], w_off + off);
                LDSM4(bl[g], w_off + TILE_B + off);
            }
            #pragma unroll
            for (int mt = 0; mt < 2; mt++)
                #pragma unroll
                for (int nt = 0; nt < 8; nt++) {
                    int g = nt >> 1, hh = nt & 1;
                    MMA_BF16(acc[mt][nt], ah[mt],  bh[g][hh], bh[g][2 + hh]);
                    MMA_BF16(acc[mt][nt], ah[mt],  bl[g][hh], bl[g][2 + hh]);
                    MMA_BF16(acc[mt][nt], al2[mt], bh[g][hh], bh[g][2 + hh]);
                }
        }
        __syncthreads();
    }

    // ---- epilogue: direct stores from fragments ----
    int g8 = lid >> 2, tig = lid & 3;
    #pragma unroll
    for (int mt = 0; mt < 2; mt++) {
        int r0 = m0 + wm0 + mt * 16 + g8;
        #pragma unroll
        for (int nt = 0; nt < 8; nt++) {
            int cl = wn0 + nt * 8 + tig * 2;     // col within block
            int c  = n0 + cl;
            float b0 = sbias[cl], b1 = sbias[cl + 1];
            float v00 = acc[mt][nt][0] + b0, v01 = acc[mt][nt][1] + b1;
            float v10 = acc[mt][nt][2] + b0, v11 = acc[mt][nt][3] + b1;
            if (MODE == 0) {
                *reinterpret_cast<float2*>(&C[(size_t)r0 * N + c])       = make_float2(v00, v01);
                *reinterpret_cast<float2*>(&C[(size_t)(r0 + 8) * N + c]) = make_float2(v10, v11);
            } else {
                v00 = fmaxf(v00, 0.f); v01 = fmaxf(v01, 0.f);
                v10 = fmaxf(v10, 0.f); v11 = fmaxf(v11, 0.f);
                bf16 h00 = __float2bfloat16_rn(v00), h01 = __float2bfloat16_rn(v01);
                bf16 h10 = __float2bfloat16_rn(v10), h11 = __float2bfloat16_rn(v11);
                bf16 l00 = __float2bfloat16_rn(v00 - __bfloat162float(h00));
                bf16 l01 = __float2bfloat16_rn(v01 - __bfloat162float(h01));
                bf16 l10 = __float2bfloat16_rn(v10 - __bfloat162float(h10));
                bf16 l11 = __float2bfloat16_rn(v11 - __bfloat162float(h11));
                uint32_t* CH = (uint32_t*)Ch; uint32_t* CL = (uint32_t*)Cl;
                size_t i0 = ((size_t)r0 * N + c) >> 1, i1 = ((size_t)(r0 + 8) * N + c) >> 1;
                CH[i0] = (uint32_t)__bfloat16_as_ushort(h00) | ((uint32_t)__bfloat16_as_ushort(h01) << 16);
                CH[i1] = (uint32_t)__bfloat16_as_ushort(h10) | ((uint32_t)__bfloat16_as_ushort(h11) << 16);
                CL[i0] = (uint32_t)__bfloat16_as_ushort(l00) | ((uint32_t)__bfloat16_as_ushort(l01) << 16);
                CL[i1] = (uint32_t)__bfloat16_as_ushort(l10) | ((uint32_t)__bfloat16_as_ushort(l11) << 16);
            }
        }
    }
}

// ---------------- fp32 -> bf16 hi/lo split ----------------------------------
__global__ void cvt_pair(const float* __restrict__ s, bf16* __restrict__ h,
                         bf16* __restrict__ l, int n) {
    int i = blockIdx.x * 256 + threadIdx.x;
    if (i >= n) return;
    float x = s[i];
    bf16 hi = __float2bfloat16_rn(x);
    h[i] = hi;
    l[i] = __float2bfloat16_rn(x - __bfloat162float(hi));
}

// ---------------- X = token_reps + PE, emitted as bf16 hi/lo ---------------
__global__ void add_pe_kernel(const float* __restrict__ tok) {
    int idx = blockIdx.x * blockDim.x + threadIdx.x;
    if (idx >= BS * H) return;
    int d   = idx % H;
    int row = idx / H;
    int pos = row % SS;
    int i2  = d & ~1;
    const float c = (float)(-9.210340371976184 / (double)H);
    float freq = expf((float)i2 * c);
    float ang  = (float)pos * freq;
    float pe   = (d & 1) ? cosf(ang) : sinf(ang);
    float x = tok[idx] + pe;
    bf16 hi = __float2bfloat16_rn(x);
    g_Xh[idx] = hi;
    g_Xl[idx] = __float2bfloat16_rn(x - __bfloat162float(hi));
}

// ---------------- q projection + fused bias --------------------------------
__global__ void proj_q_kernel(const float* __restrict__ dq,
                              const float* __restrict__ in_w,
                              const float* __restrict__ in_b,
                              const float* __restrict__ out_b) {
    int o = blockIdx.x * blockDim.x + threadIdx.x;
    if (o >= H) return;
    const float* wr = in_w + (size_t)o * H;
    float acc = in_b[o];
    #pragma unroll 4
    for (int c = 0; c < H; c++) acc += dq[c] * wr[c];
    g_qc[o]    = acc;
    g_bias2[o] = out_b[o] + dq[o];
}

// ---------------- attention: 1 block per span, warp per head ---------------
__global__ void attn_kernel(const int* __restrict__ span_ids,
                            const int* __restrict__ masks) {
    int span = blockIdx.x;
    int b    = span / NSPAN;
    __shared__ float sq[H];
    __shared__ float sattn[NH][LSPAN];
    __shared__ int sh_start, sh_len;

    int tid = threadIdx.x;           // 128
    if (tid == 0) {
        int st = span_ids[span * 2 + 0];
        int en = span_ids[span * 2 + 1];
        int mk = masks[span] ? 1 : 0;
        sh_start = st;
        sh_len   = (en - st) * mk;
    }
    for (int i = tid; i < H; i += 128) sq[i] = g_qc[i];
    __syncthreads();

    int start = sh_start, len = sh_len;
    int h = tid >> 5;
    int l = tid & 31;

    const float scale = 1.0f / sqrtf((float)HD);
    float score = -INFINITY;
    if (l < len) {
        const float* kr = g_KV + ((size_t)(b * SS + start + l)) * (2 * H) + h * HD;
        const float* qh = sq + h * HD;
        float acc = 0.f;
        #pragma unroll
        for (int d = 0; d < HD; d += 4) {
            float4 k4 = *reinterpret_cast<const float4*>(kr + d);
            acc += qh[d] * k4.x + qh[d + 1] * k4.y + qh[d + 2] * k4.z + qh[d + 3] * k4.w;
        }
        score = acc * scale;
    }
    float mx = score;
    #pragma unroll
    for (int o = 16; o > 0; o >>= 1) mx = fmaxf(mx, __shfl_xor_sync(0xffffffffu, mx, o));
    float e = (l < len) ? expf(score - mx) : 0.f;
    float sum = e;
    #pragma unroll
    for (int o = 16; o > 0; o >>= 1) sum += __shfl_xor_sync(0xffffffffu, sum, o);
    sattn[h][l] = (sum > 0.f) ? (e / sum) : 0.f;
    __syncthreads();

    const float* rowbase = g_KV + ((size_t)(b * SS + start)) * (2 * H) + H;
    for (int o = tid; o < H; o += 128) {
        int hh = o / HD;
        float acc = 0.f;
        const float* vp = rowbase + o;
        for (int l2 = 0; l2 < len; l2++)
            acc += sattn[hh][l2] * vp[(size_t)l2 * 2 * H];
        bf16 hi = __float2bfloat16_rn(acc);
        g_ctxh[(size_t)span * H + o] = hi;
        g_ctxl[(size_t)span * H + o] = __float2bfloat16_rn(acc - __bfloat162float(hi));
    }
}

// ---------------- LayerNorm; optional residual + mask + bf16 pair out ------
__global__ void ln_kernel(const float* __restrict__ in, const float* __restrict__ res,
                          const float* __restrict__ gam, const float* __restrict__ bet,
                          float* __restrict__ out, bf16* __restrict__ oh,
                          bf16* __restrict__ ol, const int* __restrict__ masks,
                          int has_res, int mask_out) {
    int row = blockIdx.x;
    __shared__ float sv[H];
    __shared__ float red[8];
    int tid = threadIdx.x;           // 256

    float s = 0.f;
    for (int i = tid; i < H; i += 256) {
        float v = in[(size_t)row * H + i];
        if (has_res) v += res[(size_t)row * H + i];
        sv[i] = v;
        s += v;
    }
    #pragma unroll
    for (int o = 16; o > 0; o >>= 1) s += __shfl_xor_sync(0xffffffffu, s, o);
    if ((tid & 31) == 0) red[tid >> 5] = s;
    __syncthreads();
    float tot = 0.f;
    #pragma unroll
    for (int w = 0; w < 8; w++) tot += red[w];
    float mean = tot / (float)H;
    __syncthreads();

    float vs = 0.f;
    for (int i = tid; i < H; i += 256) {
        float d = sv[i] - mean;
        vs += d * d;
    }
    #pragma unroll
    for (int o = 16; o > 0; o >>= 1) vs += __shfl_xor_sync(0xffffffffu, vs, o);
    if ((tid & 31) == 0) red[tid >> 5] = vs;
    __syncthreads();
    float vtot = 0.f;
    #pragma unroll
    for (int w = 0; w < 8; w++) vtot += red[w];
    float rstd = rsqrtf(vtot / (float)H + 1e-5f);

    int keep = mask_out ? (masks[row] ? 1 : 0) : 1;
    for (int i = tid; i < H; i += 256) {
        float val = (sv[i] - mean) * rstd * gam[i] + bet[i];
        val = keep ? val : 0.f;
        out[(size_t)row * H + i] = val;
        if (oh) {
            bf16 hi = __float2bfloat16_rn(val);
            oh[(size_t)row * H + i] = hi;
            ol[(size_t)row * H + i] = __float2bfloat16_rn(val - __bfloat162float(hi));
        }
    }
}

// ---------------- launch ---------------------------------------------------
extern "C" void kernel_launch(void* const* d_in, const int* in_sizes, int n_in,
                              void* d_out, int out_size) {
    const float* tok   = (const float*)d_in[0];
    const int*   sids  = (const int*)d_in[1];
    const int*   masks = (const int*)d_in[2];    // bool -> int32 on the wire
    int base = (n_in >= 15) ? 4 : 3;
    const float* dq    = (const float*)d_in[base + 0];
    const float* in_w  = (const float*)d_in[base + 1];
    const float* in_b  = (const float*)d_in[base + 2];
    const float* out_w = (const float*)d_in[base + 3];
    const float* out_b = (const float*)d_in[base + 4];
    const float* ln_g  = (const float*)d_in[base + 5];
    const float* ln_b  = (const float*)d_in[base + 6];
    const float* w1    = (const float*)d_in[base + 7];
    const float* b1    = (const float*)d_in[base + 8];
    const float* w2    = (const float*)d_in[base + 9];
    const float* b2    = (const float*)d_in[base + 10];
    float* outp = (float*)d_out;

    float *pKV, *pAo, *pY, *pFf, *pBias2;
    bf16 *pXh, *pXl, *pKWh, *pKWl, *pOWh, *pOWl, *pW1h, *pW1l, *pW2h, *pW2l;
    bf16 *pCxh, *pCxl, *pYh, *pYl, *pH1h, *pH1l;
    cudaGetSymbolAddress((void**)&pKV,   g_KV);
    cudaGetSymbolAddress((void**)&pAo,   g_ao);
    cudaGetSymbolAddress((void**)&pY,    g_y);
    cudaGetSymbolAddress((void**)&pFf,   g_ff);
    cudaGetSymbolAddress((void**)&pBias2,g_bias2);
    cudaGetSymbolAddress((void**)&pXh,   g_Xh);   cudaGetSymbolAddress((void**)&pXl,   g_Xl);
    cudaGetSymbolAddress((void**)&pKWh,  g_kvwh); cudaGetSymbolAddress((void**)&pKWl,  g_kvwl);
    cudaGetSymbolAddress((void**)&pOWh,  g_owh);  cudaGetSymbolAddress((void**)&pOWl,  g_owl);
    cudaGetSymbolAddress((void**)&pW1h,  g_w1h);  cudaGetSymbolAddress((void**)&pW1l,  g_w1l);
    cudaGetSymbolAddress((void**)&pW2h,  g_w2h);  cudaGetSymbolAddress((void**)&pW2l,  g_w2l);
    cudaGetSymbolAddress((void**)&pCxh,  g_ctxh); cudaGetSymbolAddress((void**)&pCxl,  g_ctxl);
    cudaGetSymbolAddress((void**)&pYh,   g_yh);   cudaGetSymbolAddress((void**)&pYl,   g_yl);
    cudaGetSymbolAddress((void**)&pH1h,  g_h1h);  cudaGetSymbolAddress((void**)&pH1l,  g_h1l);

    cudaFuncSetAttribute(hmma_gemm<0>, cudaFuncAttributeMaxDynamicSharedMemorySize, SMEM_TOTAL);
    cudaFuncSetAttribute(hmma_gemm<1>, cudaFuncAttributeMaxDynamicSharedMemorySize, SMEM_TOTAL);

    // prep
    add_pe_kernel<<<(BS * H + 255) / 256, 256>>>(tok);
    proj_q_kernel<<<3, 256>>>(dq, in_w, in_b, out_b);
    cvt_pair<<<(2 * H * H + 255) / 256, 256>>>(in_w + (size_t)H * H, pKWh, pKWl, 2 * H * H);
    cvt_pair<<<(H * H + 255) / 256, 256>>>(out_w, pOWh, pOWl, H * H);
    cvt_pair<<<(FFN_DIM * H + 255) / 256, 256>>>(w1, pW1h, pW1l, FFN_DIM * H);
    cvt_pair<<<(H * FFN_DIM + 255) / 256, 256>>>(w2, pW2h, pW2l, H * FFN_DIM);

    // KV projection: [4096, 1536] fp32
    hmma_gemm<0><<<dim3(1536 / 128, BS / 128), 256, SMEM_TOTAL>>>(
        pXh, pXl, pKWh, pKWl, in_b + H, pKV, nullptr, nullptr, 2 * H, H);
    // span attention -> ctx (bf16 pair)
    attn_kernel<<<BN, 128>>>(sids, masks);
    // out projection (+out_b + dummy_query): fp32 ao
    hmma_gemm<0><<<dim3(H / 128, BN / 128), 256, SMEM_TOTAL>>>(
        pCxh, pCxl, pOWh, pOWl, pBias2, pAo, nullptr, nullptr, H, H);
    // LN1 -> y fp32 + bf16 pair
    ln_kernel<<<BN, 256>>>(pAo, nullptr, ln_g, ln_b, pY, pYh, pYl, nullptr, 0, 0);
    // FFN1 + relu -> h1 bf16 pair only
    hmma_gemm<1><<<dim3(FFN_DIM / 128, BN / 128), 256, SMEM_TOTAL>>>(
        pYh, pYl, pW1h, pW1l, b1, nullptr, pH1h, pH1l, FFN_DIM, H);
    // FFN2 -> ff fp32
    hmma_gemm<0><<<dim3(H / 128, BN / 128), 256, SMEM_TOTAL>>>(
        pH1h, pH1l, pW2h, pW2l, b2, pFf, nullptr, nullptr, H, FFN_DIM);
    // LN2 (+residual y, +mask) -> output
    ln_kernel<<<BN, 256>>>(pFf, pY, ln_g, ln_b, outp, nullptr, nullptr, masks, 1, 1);
    (void)in_sizes; (void)out_size;
}

// round 6
// speedup vs baseline: 3.0007x; 1.0334x over previous
#include <cuda_runtime.h>
#include <cuda_bf16.h>
#include <math.h>
#include <stdint.h>

#define BB 8
#define SS 512
#define NSPAN 512
#define H 768
#define NH 4
#define HD 192
#define FFN_DIM 3072
#define LSPAN 32
#define BS (BB*SS)      // 4096 token rows
#define BN (BB*NSPAN)   // 4096 span rows

typedef __nv_bfloat16 bf16;

// ---------------- scratch (static device globals; no allocations) ----------
__device__ bf16  g_Xh[(size_t)BS*H], g_Xl[(size_t)BS*H];
__device__ bf16  g_kvwh[(size_t)2*H*H], g_kvwl[(size_t)2*H*H];
__device__ bf16  g_owh[(size_t)H*H],   g_owl[(size_t)H*H];
__device__ bf16  g_w1h[(size_t)FFN_DIM*H], g_w1l[(size_t)FFN_DIM*H];
__device__ bf16  g_w2h[(size_t)H*FFN_DIM], g_w2l[(size_t)H*FFN_DIM];
__device__ float g_KV[(size_t)BS*2*H];   // K cols 0..767, V cols 768..1535 (fp32)
__device__ bf16  g_ctxh[(size_t)BN*H], g_ctxl[(size_t)BN*H];
__device__ float g_ao[(size_t)BN*H];
__device__ float g_y[(size_t)BN*H];
__device__ bf16  g_yh[(size_t)BN*H], g_yl[(size_t)BN*H];
__device__ bf16  g_h1h[(size_t)BN*FFN_DIM], g_h1l[(size_t)BN*FFN_DIM];
__device__ float g_ff[(size_t)BN*H];
__device__ float g_qc[H];
__device__ float g_bias2[H];             // out_b + dummy_query

// ---------------- PTX helpers ----------------------------------------------
__device__ __forceinline__ uint32_t smem_u32(const void* p) {
    uint32_t a;
    asm("{ .reg .u64 t; cvta.to.shared.u64 t, %1; cvt.u32.u64 %0, t; }" : "=r"(a) : "l"(p));
    return a;
}
#define LDSM4(r, addr) \
    asm volatile("ldmatrix.sync.aligned.m8n8.x4.shared.b16 {%0,%1,%2,%3}, [%4];" \
        : "=r"((r)[0]), "=r"((r)[1]), "=r"((r)[2]), "=r"((r)[3]) : "r"(addr))
#define MMA_BF16(d, a, b0, b1) \
    asm volatile("mma.sync.aligned.m16n8k16.row.col.f32.bf16.bf16.f32 " \
        "{%0,%1,%2,%3}, {%4,%5,%6,%7}, {%8,%9}, {%0,%1,%2,%3};" \
        : "+f"((d)[0]), "+f"((d)[1]), "+f"((d)[2]), "+f"((d)[3]) \
        : "r"((a)[0]), "r"((a)[1]), "r"((a)[2]), "r"((a)[3]), "r"(b0), "r"(b1))
#define CP16(sdst, gsrc) \
    asm volatile("cp.async.cg.shared.global [%0], [%1], 16;" :: "r"(sdst), "l"(gsrc))
#define CP_COMMIT() asm volatile("cp.async.commit_group;" ::: "memory")
#define CP_WAIT1()  asm volatile("cp.async.wait_group 1;" ::: "memory")
#define CP_WAIT0()  asm volatile("cp.async.wait_group 0;" ::: "memory")

#define TSTRIDE 72                       // bf16 elems per smem row (64 + 8 pad)
#define TILE_B (128*TSTRIDE*2)           // 18432 B per tile
#define SMEM_TOTAL (8*TILE_B + 512)      // 2 stages x 4 tiles + bias

// ---------------- HMMA GEMM: C[M,N] = (Ah+Al)[M,K] @ (Wh+Wl)[N,K]^T + bias
// 3-term bf16 split. Block 128x128, 256 thr (8 warps, 4Mx2N), warp 32x64.
// cp.async 2-stage double buffering.
// MODE 0: fp32 out. MODE 1: relu then bf16 hi/lo pair out.
template<int MODE>
__global__ void __launch_bounds__(256, 1)
hmma_gemm(const bf16* __restrict__ Ah, const bf16* __restrict__ Al,
          const bf16* __restrict__ Wh, const bf16* __restrict__ Wl,
          const float* __restrict__ bias, float* __restrict__ C,
          bf16* __restrict__ Ch, bf16* __restrict__ Cl, int N, int K) {
    extern __shared__ char sm[];
    uint32_t sb = smem_u32(sm);
    float* sbias = (float*)(sm + 8 * TILE_B);
    int tid = threadIdx.x, wid = tid >> 5, lid = tid & 31;
    int m0 = blockIdx.y * 128, n0 = blockIdx.x * 128;
    int warp_m = wid >> 1, warp_n = wid & 1;     // 4 x 2
    int wm0 = warp_m * 32, wn0 = warp_n * 64;

    if (tid < 128) sbias[tid] = bias[n0 + tid];

    float acc[2][8][4];
    #pragma unroll
    for (int mt = 0; mt < 2; mt++)
        #pragma unroll
        for (int nt = 0; nt < 8; nt++)
            #pragma unroll
            for (int j = 0; j < 4; j++) acc[mt][nt][j] = 0.f;

    // per-thread loader coords (16B chunk per cp.async)
    int lrow = tid >> 3, lc16 = tid & 7;         // base: 256 thr covers 32 rows? no:
    // each thread handles rows lrow, lrow+32, lrow+64, lrow+96 via it-loop

    // per-thread ldmatrix base offsets (bytes, relative to buffer start)
    uint32_t a_rel = (uint32_t)(((wm0 + (lid & 15)) * TSTRIDE + ((lid >> 4) << 3)) * 2);
    uint32_t w_rel = (uint32_t)(2 * TILE_B + ((wn0 + (lid & 15)) * TSTRIDE + ((lid >> 4) << 3)) * 2);

    int nsteps = K / 64;

    // ---- async loader for K-chunk s into buffer buf ----
    auto load_chunk = [&](int s, int buf) {
        uint32_t base = sb + (uint32_t)buf * 4 * TILE_B;
        int k0 = s * 64;
        #pragma unroll
        for (int it = 0; it < 4; it++) {
            int row = lrow + it * 32;
            uint32_t so = (uint32_t)(row * TSTRIDE * 2 + lc16 * 16);
            const char* pa = (const char*)(Ah + (size_t)(m0 + row) * K + k0) + lc16 * 16;
            const char* pl = (const char*)(Al + (size_t)(m0 + row) * K + k0) + lc16 * 16;
            const char* pb = (const char*)(Wh + (size_t)(n0 + row) * K + k0) + lc16 * 16;
            const char* pc = (const char*)(Wl + (size_t)(n0 + row) * K + k0) + lc16 * 16;
            CP16(base + 0 * TILE_B + so, pa);
            CP16(base + 1 * TILE_B + so, pl);
            CP16(base + 2 * TILE_B + so, pb);
            CP16(base + 3 * TILE_B + so, pc);
        }
    };

    load_chunk(0, 0);
    CP_COMMIT();

    for (int s = 0; s < nsteps; s++) {
        int buf = s & 1;
        if (s + 1 < nsteps) {
            load_chunk(s + 1, (s + 1) & 1);
            CP_COMMIT();
            CP_WAIT1();
        } else {
            CP_WAIT0();
        }
        __syncthreads();

        uint32_t a_off = sb + (uint32_t)buf * 4 * TILE_B + a_rel;
        uint32_t w_off = sb + (uint32_t)buf * 4 * TILE_B + w_rel;
        #pragma unroll
        for (int kk = 0; kk < 4; kk++) {
            uint32_t ah[2][4], al2[2][4], bh[4][4], bl[4][4];
            #pragma unroll
            for (int t = 0; t < 2; t++) {
                uint32_t off = (uint32_t)(t * 16 * TSTRIDE * 2 + kk * 32);
                LDSM4(ah[t],  a_off + off);
                LDSM4(al2[t], a_off + TILE_B + off);
            }
            #pragma unroll
            for (int g = 0; g < 4; g++) {
                uint32_t off = (uint32_t)(g * 16 * TSTRIDE * 2 + kk * 32);
                LDSM4(bh[g], w_off + off);
                LDSM4(bl[g], w_off + TILE_B + off);
            }
            #pragma unroll
            for (int mt = 0; mt < 2; mt++)
                #pragma unroll
                for (int nt = 0; nt < 8; nt++) {
                    int g = nt >> 1, hh = nt & 1;
                    MMA_BF16(acc[mt][nt], ah[mt],  bh[g][hh], bh[g][2 + hh]);
                    MMA_BF16(acc[mt][nt], ah[mt],  bl[g][hh], bl[g][2 + hh]);
                    MMA_BF16(acc[mt][nt], al2[mt], bh[g][hh], bh[g][2 + hh]);
                }
        }
        __syncthreads();
    }

    // ---- epilogue: direct stores from fragments ----
    int g8 = lid >> 2, tig = lid & 3;
    #pragma unroll
    for (int mt = 0; mt < 2; mt++) {
        int r0 = m0 + wm0 + mt * 16 + g8;
        #pragma unroll
        for (int nt = 0; nt < 8; nt++) {
            int cl = wn0 + nt * 8 + tig * 2;     // col within block
            int c  = n0 + cl;
            float b0 = sbias[cl], b1 = sbias[cl + 1];
            float v00 = acc[mt][nt][0] + b0, v01 = acc[mt][nt][1] + b1;
            float v10 = acc[mt][nt][2] + b0, v11 = acc[mt][nt][3] + b1;
            if (MODE == 0) {
                *reinterpret_cast<float2*>(&C[(size_t)r0 * N + c])       = make_float2(v00, v01);
                *reinterpret_cast<float2*>(&C[(size_t)(r0 + 8) * N + c]) = make_float2(v10, v11);
            } else {
                v00 = fmaxf(v00, 0.f); v01 = fmaxf(v01, 0.f);
                v10 = fmaxf(v10, 0.f); v11 = fmaxf(v11, 0.f);
                bf16 h00 = __float2bfloat16_rn(v00), h01 = __float2bfloat16_rn(v01);
                bf16 h10 = __float2bfloat16_rn(v10), h11 = __float2bfloat16_rn(v11);
                bf16 l00 = __float2bfloat16_rn(v00 - __bfloat162float(h00));
                bf16 l01 = __float2bfloat16_rn(v01 - __bfloat162float(h01));
                bf16 l10 = __float2bfloat16_rn(v10 - __bfloat162float(h10));
                bf16 l11 = __float2bfloat16_rn(v11 - __bfloat162float(h11));
                uint32_t* CH = (uint32_t*)Ch; uint32_t* CL = (uint32_t*)Cl;
                size_t i0 = ((size_t)r0 * N + c) >> 1, i1 = ((size_t)(r0 + 8) * N + c) >> 1;
                CH[i0] = (uint32_t)__bfloat16_as_ushort(h00) | ((uint32_t)__bfloat16_as_ushort(h01) << 16);
                CH[i1] = (uint32_t)__bfloat16_as_ushort(h10) | ((uint32_t)__bfloat16_as_ushort(h11) << 16);
                CL[i0] = (uint32_t)__bfloat16_as_ushort(l00) | ((uint32_t)__bfloat16_as_ushort(l01) << 16);
                CL[i1] = (uint32_t)__bfloat16_as_ushort(l10) | ((uint32_t)__bfloat16_as_ushort(l11) << 16);
            }
        }
    }
}

// ---------------- fp32 -> bf16 hi/lo split ----------------------------------
__global__ void cvt_pair(const float* __restrict__ s, bf16* __restrict__ h,
                         bf16* __restrict__ l, int n) {
    int i = blockIdx.x * 256 + threadIdx.x;
    if (i >= n) return;
    float x = s[i];
    bf16 hi = __float2bfloat16_rn(x);
    h[i] = hi;
    l[i] = __float2bfloat16_rn(x - __bfloat162float(hi));
}

// ---------------- X = token_reps + PE, emitted as bf16 hi/lo ---------------
__global__ void add_pe_kernel(const float* __restrict__ tok) {
    int idx = blockIdx.x * blockDim.x + threadIdx.x;
    if (idx >= BS * H) return;
    int d   = idx % H;
    int row = idx / H;
    int pos = row % SS;
    int i2  = d & ~1;
    const float c = (float)(-9.210340371976184 / (double)H);
    float freq = expf((float)i2 * c);
    float ang  = (float)pos * freq;
    float pe   = (d & 1) ? cosf(ang) : sinf(ang);
    float x = tok[idx] + pe;
    bf16 hi = __float2bfloat16_rn(x);
    g_Xh[idx] = hi;
    g_Xl[idx] = __float2bfloat16_rn(x - __bfloat162float(hi));
}

// ---------------- q projection + fused bias --------------------------------
__global__ void proj_q_kernel(const float* __restrict__ dq,
                              const float* __restrict__ in_w,
                              const float* __restrict__ in_b,
                              const float* __restrict__ out_b) {
    int o = blockIdx.x * blockDim.x + threadIdx.x;
    if (o >= H) return;
    const float* wr = in_w + (size_t)o * H;
    float acc = in_b[o];
    #pragma unroll 4
    for (int c = 0; c < H; c++) acc += dq[c] * wr[c];
    g_qc[o]    = acc;
    g_bias2[o] = out_b[o] + dq[o];
}

// ---------------- attention: 1 block per span, warp per head ---------------
__global__ void attn_kernel(const int* __restrict__ span_ids,
                            const int* __restrict__ masks) {
    int span = blockIdx.x;
    int b    = span / NSPAN;
    __shared__ float sq[H];
    __shared__ float sattn[NH][LSPAN];
    __shared__ int sh_start, sh_len;

    int tid = threadIdx.x;           // 128
    if (tid == 0) {
        int st = span_ids[span * 2 + 0];
        int en = span_ids[span * 2 + 1];
        int mk = masks[span] ? 1 : 0;
        sh_start = st;
        sh_len   = (en - st) * mk;
    }
    for (int i = tid; i < H; i += 128) sq[i] = g_qc[i];
    __syncthreads();

    int start = sh_start, len = sh_len;
    int h = tid >> 5;
    int l = tid & 31;

    const float scale = 1.0f / sqrtf((float)HD);
    float score = -INFINITY;
    if (l < len) {
        const float* kr = g_KV + ((size_t)(b * SS + start + l)) * (2 * H) + h * HD;
        const float* qh = sq + h * HD;
        float acc = 0.f;
        #pragma unroll
        for (int d = 0; d < HD; d += 4) {
            float4 k4 = *reinterpret_cast<const float4*>(kr + d);
            acc += qh[d] * k4.x + qh[d + 1] * k4.y + qh[d + 2] * k4.z + qh[d + 3] * k4.w;
        }
        score = acc * scale;
    }
    float mx = score;
    #pragma unroll
    for (int o = 16; o > 0; o >>= 1) mx = fmaxf(mx, __shfl_xor_sync(0xffffffffu, mx, o));
    float e = (l < len) ? expf(score - mx) : 0.f;
    float sum = e;
    #pragma unroll
    for (int o = 16; o > 0; o >>= 1) sum += __shfl_xor_sync(0xffffffffu, sum, o);
    sattn[h][l] = (sum > 0.f) ? (e / sum) : 0.f;
    __syncthreads();

    const float* rowbase = g_KV + ((size_t)(b * SS + start)) * (2 * H) + H;
    for (int o = tid; o < H; o += 128) {
        int hh = o / HD;
        float acc = 0.f;
        const float* vp = rowbase + o;
        for (int l2 = 0; l2 < len; l2++)
            acc += sattn[hh][l2] * vp[(size_t)l2 * 2 * H];
        bf16 hi = __float2bfloat16_rn(acc);
        g_ctxh[(size_t)span * H + o] = hi;
        g_ctxl[(size_t)span * H + o] = __float2bfloat16_rn(acc - __bfloat162float(hi));
    }
}

// ---------------- LayerNorm; optional residual + mask + bf16 pair out ------
__global__ void ln_kernel(const float* __restrict__ in, const float* __restrict__ res,
                          const float* __restrict__ gam, const float* __restrict__ bet,
                          float* __restrict__ out, bf16* __restrict__ oh,
                          bf16* __restrict__ ol, const int* __restrict__ masks,
                          int has_res, int mask_out) {
    int row = blockIdx.x;
    __shared__ float sv[H];
    __shared__ float red[8];
    int tid = threadIdx.x;           // 256

    float s = 0.f;
    for (int i = tid; i < H; i += 256) {
        float v = in[(size_t)row * H + i];
        if (has_res) v += res[(size_t)row * H + i];
        sv[i] = v;
        s += v;
    }
    #pragma unroll
    for (int o = 16; o > 0; o >>= 1) s += __shfl_xor_sync(0xffffffffu, s, o);
    if ((tid & 31) == 0) red[tid >> 5] = s;
    __syncthreads();
    float tot = 0.f;
    #pragma unroll
    for (int w = 0; w < 8; w++) tot += red[w];
    float mean = tot / (float)H;
    __syncthreads();

    float vs = 0.f;
    for (int i = tid; i < H; i += 256) {
        float d = sv[i] - mean;
        vs += d * d;
    }
    #pragma unroll
    for (int o = 16; o > 0; o >>= 1) vs += __shfl_xor_sync(0xffffffffu, vs, o);
    if ((tid & 31) == 0) red[tid >> 5] = vs;
    __syncthreads();
    float vtot = 0.f;
    #pragma unroll
    for (int w = 0; w < 8; w++) vtot += red[w];
    float rstd = rsqrtf(vtot / (float)H + 1e-5f);

    int keep = mask_out ? (masks[row] ? 1 : 0) : 1;
    for (int i = tid; i < H; i += 256) {
        float val = (sv[i] - mean) * rstd * gam[i] + bet[i];
        val = keep ? val : 0.f;
        out[(size_t)row * H + i] = val;
        if (oh) {
            bf16 hi = __float2bfloat16_rn(val);
            oh[(size_t)row * H + i] = hi;
            ol[(size_t)row * H + i] = __float2bfloat16_rn(val - __bfloat162float(hi));
        }
    }
}

// ---------------- launch ---------------------------------------------------
extern "C" void kernel_launch(void* const* d_in, const int* in_sizes, int n_in,
                              void* d_out, int out_size) {
    const float* tok   = (const float*)d_in[0];
    const int*   sids  = (const int*)d_in[1];
    const int*   masks = (const int*)d_in[2];    // bool -> int32 on the wire
    int base = (n_in >= 15) ? 4 : 3;
    const float* dq    = (const float*)d_in[base + 0];
    const float* in_w  = (const float*)d_in[base + 1];
    const float* in_b  = (const float*)d_in[base + 2];
    const float* out_w = (const float*)d_in[base + 3];
    const float* out_b = (const float*)d_in[base + 4];
    const float* ln_g  = (const float*)d_in[base + 5];
    const float* ln_b  = (const float*)d_in[base + 6];
    const float* w1    = (const float*)d_in[base + 7];
    const float* b1    = (const float*)d_in[base + 8];
    const float* w2    = (const float*)d_in[base + 9];
    const float* b2    = (const float*)d_in[base + 10];
    float* outp = (float*)d_out;

    float *pKV, *pAo, *pY, *pFf, *pBias2;
    bf16 *pXh, *pXl, *pKWh, *pKWl, *pOWh, *pOWl, *pW1h, *pW1l, *pW2h, *pW2l;
    bf16 *pCxh, *pCxl, *pYh, *pYl, *pH1h, *pH1l;
    cudaGetSymbolAddress((void**)&pKV,   g_KV);
    cudaGetSymbolAddress((void**)&pAo,   g_ao);
    cudaGetSymbolAddress((void**)&pY,    g_y);
    cudaGetSymbolAddress((void**)&pFf,   g_ff);
    cudaGetSymbolAddress((void**)&pBias2,g_bias2);
    cudaGetSymbolAddress((void**)&pXh,   g_Xh);   cudaGetSymbolAddress((void**)&pXl,   g_Xl);
    cudaGetSymbolAddress((void**)&pKWh,  g_kvwh); cudaGetSymbolAddress((void**)&pKWl,  g_kvwl);
    cudaGetSymbolAddress((void**)&pOWh,  g_owh);  cudaGetSymbolAddress((void**)&pOWl,  g_owl);
    cudaGetSymbolAddress((void**)&pW1h,  g_w1h);  cudaGetSymbolAddress((void**)&pW1l,  g_w1l);
    cudaGetSymbolAddress((void**)&pW2h,  g_w2h);  cudaGetSymbolAddress((void**)&pW2l,  g_w2l);
    cudaGetSymbolAddress((void**)&pCxh,  g_ctxh); cudaGetSymbolAddress((void**)&pCxl,  g_ctxl);
    cudaGetSymbolAddress((void**)&pYh,   g_yh);   cudaGetSymbolAddress((void**)&pYl,   g_yl);
    cudaGetSymbolAddress((void**)&pH1h,  g_h1h);  cudaGetSymbolAddress((void**)&pH1l,  g_h1l);

    cudaFuncSetAttribute(hmma_gemm<0>, cudaFuncAttributeMaxDynamicSharedMemorySize, SMEM_TOTAL);
    cudaFuncSetAttribute(hmma_gemm<1>, cudaFuncAttributeMaxDynamicSharedMemorySize, SMEM_TOTAL);

    // prep
    add_pe_kernel<<<(BS * H + 255) / 256, 256>>>(tok);
    proj_q_kernel<<<3, 256>>>(dq, in_w, in_b, out_b);
    cvt_pair<<<(2 * H * H + 255) / 256, 256>>>(in_w + (size_t)H * H, pKWh, pKWl, 2 * H * H);
    cvt_pair<<<(H * H + 255) / 256, 256>>>(out_w, pOWh, pOWl, H * H);
    cvt_pair<<<(FFN_DIM * H + 255) / 256, 256>>>(w1, pW1h, pW1l, FFN_DIM * H);
    cvt_pair<<<(H * FFN_DIM + 255) / 256, 256>>>(w2, pW2h, pW2l, H * FFN_DIM);

    // KV projection: [4096, 1536] fp32
    hmma_gemm<0><<<dim3(1536 / 128, BS / 128), 256, SMEM_TOTAL>>>(
        pXh, pXl, pKWh, pKWl, in_b + H, pKV, nullptr, nullptr, 2 * H, H);
    // span attention -> ctx (bf16 pair)
    attn_kernel<<<BN, 128>>>(sids, masks);
    // out projection (+out_b + dummy_query): fp32 ao
    hmma_gemm<0><<<dim3(H / 128, BN / 128), 256, SMEM_TOTAL>>>(
        pCxh, pCxl, pOWh, pOWl, pBias2, pAo, nullptr, nullptr, H, H);
    // LN1 -> y fp32 + bf16 pair
    ln_kernel<<<BN, 256>>>(pAo, nullptr, ln_g, ln_b, pY, pYh, pYl, nullptr, 0, 0);
    // FFN1 + relu -> h1 bf16 pair only
    hmma_gemm<1><<<dim3(FFN_DIM / 128, BN / 128), 256, SMEM_TOTAL>>>(
        pYh, pYl, pW1h, pW1l, b1, nullptr, pH1h, pH1l, FFN_DIM, H);
    // FFN2 -> ff fp32
    hmma_gemm<0><<<dim3(H / 128, BN / 128), 256, SMEM_TOTAL>>>(
        pH1h, pH1l, pW2h, pW2l, b2, pFf, nullptr, nullptr, H, FFN_DIM);
    // LN2 (+residual y, +mask) -> output
    ln_kernel<<<BN, 256>>>(pFf, pY, ln_g, ln_b, outp, nullptr, nullptr, masks, 1, 1);
    (void)in_sizes; (void)out_size;
}

// round 7
// speedup vs baseline: 3.0135x; 1.0043x over previous
#include <cuda_runtime.h>
#include <cuda_bf16.h>
#include <math.h>
#include <stdint.h>

#define BB 8
#define SS 512
#define NSPAN 512
#define H 768
#define NH 4
#define HD 192
#define FFN_DIM 3072
#define LSPAN 32
#define BS (BB*SS)      // 4096 token rows
#define BN (BB*NSPAN)   // 4096 span rows

typedef __nv_bfloat16 bf16;

// ---------------- scratch (static device globals; no allocations) ----------
__device__ bf16  g_Xh[(size_t)BS*H], g_Xl[(size_t)BS*H];
__device__ bf16  g_kvwh[(size_t)2*H*H], g_kvwl[(size_t)2*H*H];
__device__ bf16  g_owh[(size_t)H*H],   g_owl[(size_t)H*H];
__device__ bf16  g_w1h[(size_t)FFN_DIM*H], g_w1l[(size_t)FFN_DIM*H];
__device__ bf16  g_w2h[(size_t)H*FFN_DIM], g_w2l[(size_t)H*FFN_DIM];
__device__ float g_KV[(size_t)BS*2*H];   // K cols 0..767, V cols 768..1535 (fp32)
__device__ bf16  g_ctxh[(size_t)BN*H], g_ctxl[(size_t)BN*H];
__device__ float g_ao[(size_t)BN*H];
__device__ float g_y[(size_t)BN*H];
__device__ bf16  g_yh[(size_t)BN*H], g_yl[(size_t)BN*H];
__device__ bf16  g_h1h[(size_t)BN*FFN_DIM], g_h1l[(size_t)BN*FFN_DIM];
__device__ float g_ff[(size_t)BN*H];
__device__ float g_qc[H];
__device__ float g_bias2[H];             // out_b + dummy_query

// ---------------- PTX helpers ----------------------------------------------
__device__ __forceinline__ uint32_t smem_u32(const void* p) {
    uint32_t a;
    asm("{ .reg .u64 t; cvta.to.shared.u64 t, %1; cvt.u32.u64 %0, t; }" : "=r"(a) : "l"(p));
    return a;
}
#define LDSM4(r, addr) \
    asm volatile("ldmatrix.sync.aligned.m8n8.x4.shared.b16 {%0,%1,%2,%3}, [%4];" \
        : "=r"((r)[0]), "=r"((r)[1]), "=r"((r)[2]), "=r"((r)[3]) : "r"(addr))
#define MMA_BF16(d, a, b0, b1) \
    asm volatile("mma.sync.aligned.m16n8k16.row.col.f32.bf16.bf16.f32 " \
        "{%0,%1,%2,%3}, {%4,%5,%6,%7}, {%8,%9}, {%0,%1,%2,%3};" \
        : "+f"((d)[0]), "+f"((d)[1]), "+f"((d)[2]), "+f"((d)[3]) \
        : "r"((a)[0]), "r"((a)[1]), "r"((a)[2]), "r"((a)[3]), "r"(b0), "r"(b1))
#define CP16(sdst, gsrc) \
    asm volatile("cp.async.cg.shared.global [%0], [%1], 16;" :: "r"(sdst), "l"(gsrc))
#define CP_COMMIT() asm volatile("cp.async.commit_group;" ::: "memory")
#define CP_WAIT1()  asm volatile("cp.async.wait_group 1;" ::: "memory")
#define CP_WAIT0()  asm volatile("cp.async.wait_group 0;" ::: "memory")

#define TSTRIDE 72                       // bf16 elems per smem row (64 + 8 pad)
#define TILE_B (128*TSTRIDE*2)           // 18432 B per tile
#define SMEM_TOTAL (8*TILE_B + 512)      // 2 stages x 4 tiles + bias

// ---------------- HMMA GEMM: C[M,N] = (Ah+Al)[M,K] @ (Wh+Wl)[N,K]^T + bias
// 3-term bf16 split. Block 128x128, 512 thr (16 warps, 4Mx4N), warp 32x32.
// cp.async 2-stage double buffering.
// MODE 0: fp32 out. MODE 1: relu then bf16 hi/lo pair out.
template<int MODE>
__global__ void __launch_bounds__(512, 1)
hmma_gemm(const bf16* __restrict__ Ah, const bf16* __restrict__ Al,
          const bf16* __restrict__ Wh, const bf16* __restrict__ Wl,
          const float* __restrict__ bias, float* __restrict__ C,
          bf16* __restrict__ Ch, bf16* __restrict__ Cl, int N, int K) {
    extern __shared__ char sm[];
    uint32_t sb = smem_u32(sm);
    float* sbias = (float*)(sm + 8 * TILE_B);
    int tid = threadIdx.x, wid = tid >> 5, lid = tid & 31;
    int m0 = blockIdx.y * 128, n0 = blockIdx.x * 128;
    int warp_m = wid >> 2, warp_n = wid & 3;     // 4 x 4
    int wm0 = warp_m * 32, wn0 = warp_n * 32;

    if (tid < 128) sbias[tid] = bias[n0 + tid];

    float acc[2][4][4];
    #pragma unroll
    for (int mt = 0; mt < 2; mt++)
        #pragma unroll
        for (int nt = 0; nt < 4; nt++)
            #pragma unroll
            for (int j = 0; j < 4; j++) acc[mt][nt][j] = 0.f;

    // per-thread loader coords (16B chunk per cp.async); 512 thr cover 64 rows
    int lrow = tid >> 3, lc16 = tid & 7;

    // per-thread ldmatrix base offsets (bytes, relative to buffer start)
    uint32_t a_rel = (uint32_t)(((wm0 + (lid & 15)) * TSTRIDE + ((lid >> 4) << 3)) * 2);
    uint32_t w_rel = (uint32_t)(2 * TILE_B + ((wn0 + (lid & 15)) * TSTRIDE + ((lid >> 4) << 3)) * 2);

    int nsteps = K / 64;

    auto load_chunk = [&](int s, int buf) {
        uint32_t base = sb + (uint32_t)buf * 4 * TILE_B;
        int k0 = s * 64;
        #pragma unroll
        for (int it = 0; it < 2; it++) {
            int row = lrow + it * 64;
            uint32_t so = (uint32_t)(row * TSTRIDE * 2 + lc16 * 16);
            const char* pa = (const char*)(Ah + (size_t)(m0 + row) * K + k0) + lc16 * 16;
            const char* pl = (const char*)(Al + (size_t)(m0 + row) * K + k0) + lc16 * 16;
            const char* pb = (const char*)(Wh + (size_t)(n0 + row) * K + k0) + lc16 * 16;
            const char* pc = (const char*)(Wl + (size_t)(n0 + row) * K + k0) + lc16 * 16;
            CP16(base + 0 * TILE_B + so, pa);
            CP16(base + 1 * TILE_B + so, pl);
            CP16(base + 2 * TILE_B + so, pb);
            CP16(base + 3 * TILE_B + so, pc);
        }
    };

    load_chunk(0, 0);
    CP_COMMIT();

    for (int s = 0; s < nsteps; s++) {
        int buf = s & 1;
        if (s + 1 < nsteps) {
            load_chunk(s + 1, (s + 1) & 1);
            CP_COMMIT();
            CP_WAIT1();
        } else {
            CP_WAIT0();
        }
        __syncthreads();

        uint32_t a_off = sb + (uint32_t)buf * 4 * TILE_B + a_rel;
        uint32_t w_off = sb + (uint32_t)buf * 4 * TILE_B + w_rel;
        #pragma unroll
        for (int kk = 0; kk < 4; kk++) {
            uint32_t ah[2][4], al2[2][4], bh[2][4], bl[2][4];
            #pragma unroll
            for (int t = 0; t < 2; t++) {
                uint32_t off = (uint32_t)(t * 16 * TSTRIDE * 2 + kk * 32);
                LDSM4(ah[t],  a_off + off);
                LDSM4(al2[t], a_off + TILE_B + off);
                LDSM4(bh[t],  w_off + off);
                LDSM4(bl[t],  w_off + TILE_B + off);
            }
            #pragma unroll
            for (int mt = 0; mt < 2; mt++)
                #pragma unroll
                for (int nt = 0; nt < 4; nt++) {
                    int g = nt >> 1, hh = nt & 1;
                    MMA_BF16(acc[mt][nt], ah[mt],  bh[g][hh], bh[g][2 + hh]);
                    MMA_BF16(acc[mt][nt], ah[mt],  bl[g][hh], bl[g][2 + hh]);
                    MMA_BF16(acc[mt][nt], al2[mt], bh[g][hh], bh[g][2 + hh]);
                }
        }
        __syncthreads();
    }

    // ---- epilogue: direct stores from fragments ----
    int g8 = lid >> 2, tig = lid & 3;
    #pragma unroll
    for (int mt = 0; mt < 2; mt++) {
        int r0 = m0 + wm0 + mt * 16 + g8;
        #pragma unroll
        for (int nt = 0; nt < 4; nt++) {
            int cl = wn0 + nt * 8 + tig * 2;     // col within block
            int c  = n0 + cl;
            float b0 = sbias[cl], b1 = sbias[cl + 1];
            float v00 = acc[mt][nt][0] + b0, v01 = acc[mt][nt][1] + b1;
            float v10 = acc[mt][nt][2] + b0, v11 = acc[mt][nt][3] + b1;
            if (MODE == 0) {
                *reinterpret_cast<float2*>(&C[(size_t)r0 * N + c])       = make_float2(v00, v01);
                *reinterpret_cast<float2*>(&C[(size_t)(r0 + 8) * N + c]) = make_float2(v10, v11);
            } else {
                v00 = fmaxf(v00, 0.f); v01 = fmaxf(v01, 0.f);
                v10 = fmaxf(v10, 0.f); v11 = fmaxf(v11, 0.f);
                bf16 h00 = __float2bfloat16_rn(v00), h01 = __float2bfloat16_rn(v01);
                bf16 h10 = __float2bfloat16_rn(v10), h11 = __float2bfloat16_rn(v11);
                bf16 l00 = __float2bfloat16_rn(v00 - __bfloat162float(h00));
                bf16 l01 = __float2bfloat16_rn(v01 - __bfloat162float(h01));
                bf16 l10 = __float2bfloat16_rn(v10 - __bfloat162float(h10));
                bf16 l11 = __float2bfloat16_rn(v11 - __bfloat162float(h11));
                uint32_t* CH = (uint32_t*)Ch; uint32_t* CL = (uint32_t*)Cl;
                size_t i0 = ((size_t)r0 * N + c) >> 1, i1 = ((size_t)(r0 + 8) * N + c) >> 1;
                CH[i0] = (uint32_t)__bfloat16_as_ushort(h00) | ((uint32_t)__bfloat16_as_ushort(h01) << 16);
                CH[i1] = (uint32_t)__bfloat16_as_ushort(h10) | ((uint32_t)__bfloat16_as_ushort(h11) << 16);
                CL[i0] = (uint32_t)__bfloat16_as_ushort(l00) | ((uint32_t)__bfloat16_as_ushort(l01) << 16);
                CL[i1] = (uint32_t)__bfloat16_as_ushort(l10) | ((uint32_t)__bfloat16_as_ushort(l11) << 16);
            }
        }
    }
}

// ---------------- fp32 -> bf16 hi/lo split ----------------------------------
__global__ void cvt_pair(const float* __restrict__ s, bf16* __restrict__ h,
                         bf16* __restrict__ l, int n) {
    int i = blockIdx.x * 256 + threadIdx.x;
    if (i >= n) return;
    float x = s[i];
    bf16 hi = __float2bfloat16_rn(x);
    h[i] = hi;
    l[i] = __float2bfloat16_rn(x - __bfloat162float(hi));
}

// ---------------- X = token_reps + PE, emitted as bf16 hi/lo ---------------
__global__ void add_pe_kernel(const float* __restrict__ tok) {
    int idx = blockIdx.x * blockDim.x + threadIdx.x;
    if (idx >= BS * H) return;
    int d   = idx % H;
    int row = idx / H;
    int pos = row % SS;
    int i2  = d & ~1;
    const float c = (float)(-9.210340371976184 / (double)H);
    float freq = expf((float)i2 * c);
    float ang  = (float)pos * freq;
    float pe   = (d & 1) ? cosf(ang) : sinf(ang);
    float x = tok[idx] + pe;
    bf16 hi = __float2bfloat16_rn(x);
    g_Xh[idx] = hi;
    g_Xl[idx] = __float2bfloat16_rn(x - __bfloat162float(hi));
}

// ---------------- q projection + fused bias --------------------------------
__global__ void proj_q_kernel(const float* __restrict__ dq,
                              const float* __restrict__ in_w,
                              const float* __restrict__ in_b,
                              const float* __restrict__ out_b) {
    int o = blockIdx.x * blockDim.x + threadIdx.x;
    if (o >= H) return;
    const float* wr = in_w + (size_t)o * H;
    float acc = in_b[o];
    #pragma unroll 4
    for (int c = 0; c < H; c++) acc += dq[c] * wr[c];
    g_qc[o]    = acc;
    g_bias2[o] = out_b[o] + dq[o];
}

// ---------------- attention: 1 block per span, warp per head ---------------
__global__ void attn_kernel(const int* __restrict__ span_ids,
                            const int* __restrict__ masks) {
    int span = blockIdx.x;
    int b    = span / NSPAN;
    __shared__ float sq[H];
    __shared__ float sattn[NH][LSPAN];
    __shared__ int sh_start, sh_len;

    int tid = threadIdx.x;           // 128
    if (tid == 0) {
        int st = span_ids[span * 2 + 0];
        int en = span_ids[span * 2 + 1];
        int mk = masks[span] ? 1 : 0;
        sh_start = st;
        sh_len   = (en - st) * mk;
    }
    for (int i = tid; i < H; i += 128) sq[i] = g_qc[i];
    __syncthreads();

    int start = sh_start, len = sh_len;
    int h = tid >> 5;
    int l = tid & 31;

    const float scale = 1.0f / sqrtf((float)HD);
    float score = -INFINITY;
    if (l < len) {
        const float* kr = g_KV + ((size_t)(b * SS + start + l)) * (2 * H) + h * HD;
        const float* qh = sq + h * HD;
        float acc = 0.f;
        #pragma unroll
        for (int d = 0; d < HD; d += 4) {
            float4 k4 = *reinterpret_cast<const float4*>(kr + d);
            acc += qh[d] * k4.x + qh[d + 1] * k4.y + qh[d + 2] * k4.z + qh[d + 3] * k4.w;
        }
        score = acc * scale;
    }
    float mx = score;
    #pragma unroll
    for (int o = 16; o > 0; o >>= 1) mx = fmaxf(mx, __shfl_xor_sync(0xffffffffu, mx, o));
    float e = (l < len) ? expf(score - mx) : 0.f;
    float sum = e;
    #pragma unroll
    for (int o = 16; o > 0; o >>= 1) sum += __shfl_xor_sync(0xffffffffu, sum, o);
    sattn[h][l] = (sum > 0.f) ? (e / sum) : 0.f;
    __syncthreads();

    const float* rowbase = g_KV + ((size_t)(b * SS + start)) * (2 * H) + H;
    for (int o = tid; o < H; o += 128) {
        int hh = o / HD;
        float acc = 0.f;
        const float* vp = rowbase + o;
        for (int l2 = 0; l2 < len; l2++)
            acc += sattn[hh][l2] * vp[(size_t)l2 * 2 * H];
        bf16 hi = __float2bfloat16_rn(acc);
        g_ctxh[(size_t)span * H + o] = hi;
        g_ctxl[(size_t)span * H + o] = __float2bfloat16_rn(acc - __bfloat162float(hi));
    }
}

// ---------------- LayerNorm; optional residual + mask + bf16 pair out ------
__global__ void ln_kernel(const float* __restrict__ in, const float* __restrict__ res,
                          const float* __restrict__ gam, const float* __restrict__ bet,
                          float* __restrict__ out, bf16* __restrict__ oh,
                          bf16* __restrict__ ol, const int* __restrict__ masks,
                          int has_res, int mask_out) {
    int row = blockIdx.x;
    __shared__ float sv[H];
    __shared__ float red[8];
    int tid = threadIdx.x;           // 256

    float s = 0.f;
    for (int i = tid; i < H; i += 256) {
        float v = in[(size_t)row * H + i];
        if (has_res) v += res[(size_t)row * H + i];
        sv[i] = v;
        s += v;
    }
    #pragma unroll
    for (int o = 16; o > 0; o >>= 1) s += __shfl_xor_sync(0xffffffffu, s, o);
    if ((tid & 31) == 0) red[tid >> 5] = s;
    __syncthreads();
    float tot = 0.f;
    #pragma unroll
    for (int w = 0; w < 8; w++) tot += red[w];
    float mean = tot / (float)H;
    __syncthreads();

    float vs = 0.f;
    for (int i = tid; i < H; i += 256) {
        float d = sv[i] - mean;
        vs += d * d;
    }
    #pragma unroll
    for (int o = 16; o > 0; o >>= 1) vs += __shfl_xor_sync(0xffffffffu, vs, o);
    if ((tid & 31) == 0) red[tid >> 5] = vs;
    __syncthreads();
    float vtot = 0.f;
    #pragma unroll
    for (int w = 0; w < 8; w++) vtot += red[w];
    float rstd = rsqrtf(vtot / (float)H + 1e-5f);

    int keep = mask_out ? (masks[row] ? 1 : 0) : 1;
    for (int i = tid; i < H; i += 256) {
        float val = (sv[i] - mean) * rstd * gam[i] + bet[i];
        val = keep ? val : 0.f;
        out[(size_t)row * H + i] = val;
        if (oh) {
            bf16 hi = __float2bfloat16_rn(val);
            oh[(size_t)row * H + i] = hi;
            ol[(size_t)row * H + i] = __float2bfloat16_rn(val - __bfloat162float(hi));
        }
    }
}

// ---------------- launch ---------------------------------------------------
extern "C" void kernel_launch(void* const* d_in, const int* in_sizes, int n_in,
                              void* d_out, int out_size) {
    const float* tok   = (const float*)d_in[0];
    const int*   sids  = (const int*)d_in[1];
    const int*   masks = (const int*)d_in[2];    // bool -> int32 on the wire
    int base = (n_in >= 15) ? 4 : 3;
    const float* dq    = (const float*)d_in[base + 0];
    const float* in_w  = (const float*)d_in[base + 1];
    const float* in_b  = (const float*)d_in[base + 2];
    const float* out_w = (const float*)d_in[base + 3];
    const float* out_b = (const float*)d_in[base + 4];
    const float* ln_g  = (const float*)d_in[base + 5];
    const float* ln_b  = (const float*)d_in[base + 6];
    const float* w1    = (const float*)d_in[base + 7];
    const float* b1    = (const float*)d_in[base + 8];
    const float* w2    = (const float*)d_in[base + 9];
    const float* b2    = (const float*)d_in[base + 10];
    float* outp = (float*)d_out;

    float *pKV, *pAo, *pY, *pFf, *pBias2;
    bf16 *pXh, *pXl, *pKWh, *pKWl, *pOWh, *pOWl, *pW1h, *pW1l, *pW2h, *pW2l;
    bf16 *pCxh, *pCxl, *pYh, *pYl, *pH1h, *pH1l;
    cudaGetSymbolAddress((void**)&pKV,   g_KV);
    cudaGetSymbolAddress((void**)&pAo,   g_ao);
    cudaGetSymbolAddress((void**)&pY,    g_y);
    cudaGetSymbolAddress((void**)&pFf,   g_ff);
    cudaGetSymbolAddress((void**)&pBias2,g_bias2);
    cudaGetSymbolAddress((void**)&pXh,   g_Xh);   cudaGetSymbolAddress((void**)&pXl,   g_Xl);
    cudaGetSymbolAddress((void**)&pKWh,  g_kvwh); cudaGetSymbolAddress((void**)&pKWl,  g_kvwl);
    cudaGetSymbolAddress((void**)&pOWh,  g_owh);  cudaGetSymbolAddress((void**)&pOWl,  g_owl);
    cudaGetSymbolAddress((void**)&pW1h,  g_w1h);  cudaGetSymbolAddress((void**)&pW1l,  g_w1l);
    cudaGetSymbolAddress((void**)&pW2h,  g_w2h);  cudaGetSymbolAddress((void**)&pW2l,  g_w2l);
    cudaGetSymbolAddress((void**)&pCxh,  g_ctxh); cudaGetSymbolAddress((void**)&pCxl,  g_ctxl);
    cudaGetSymbolAddress((void**)&pYh,   g_yh);   cudaGetSymbolAddress((void**)&pYl,   g_yl);
    cudaGetSymbolAddress((void**)&pH1h,  g_h1h);  cudaGetSymbolAddress((void**)&pH1l,  g_h1l);

    cudaFuncSetAttribute(hmma_gemm<0>, cudaFuncAttributeMaxDynamicSharedMemorySize, SMEM_TOTAL);
    cudaFuncSetAttribute(hmma_gemm<1>, cudaFuncAttributeMaxDynamicSharedMemorySize, SMEM_TOTAL);

    // prep (ordered so the 6th launch below is the KV GEMM -> ncu profiles it)
    add_pe_kernel<<<(BS * H + 255) / 256, 256>>>(tok);                               // 1
    proj_q_kernel<<<3, 256>>>(dq, in_w, in_b, out_b);                                // 2
    cvt_pair<<<(2 * H * H + 255) / 256, 256>>>(in_w + (size_t)H * H, pKWh, pKWl, 2 * H * H); // 3
    cvt_pair<<<(H * H + 255) / 256, 256>>>(out_w, pOWh, pOWl, H * H);                // 4
    cvt_pair<<<(FFN_DIM * H + 255) / 256, 256>>>(w1, pW1h, pW1l, FFN_DIM * H);       // 5

    // KV projection: [4096, 1536] fp32                                              // 6 (profiled)
    hmma_gemm<0><<<dim3(1536 / 128, BS / 128), 512, SMEM_TOTAL>>>(
        pXh, pXl, pKWh, pKWl, in_b + H, pKV, nullptr, nullptr, 2 * H, H);
    // span attention -> ctx (bf16 pair)
    attn_kernel<<<BN, 128>>>(sids, masks);
    // out projection (+out_b + dummy_query): fp32 ao
    hmma_gemm<0><<<dim3(H / 128, BN / 128), 512, SMEM_TOTAL>>>(
        pCxh, pCxl, pOWh, pOWl, pBias2, pAo, nullptr, nullptr, H, H);
    // LN1 -> y fp32 + bf16 pair
    ln_kernel<<<BN, 256>>>(pAo, nullptr, ln_g, ln_b, pY, pYh, pYl, nullptr, 0, 0);
    // w2 conversion (moved here; needed only by FFN2)
    cvt_pair<<<(H * FFN_DIM + 255) / 256, 256>>>(w2, pW2h, pW2l, H * FFN_DIM);
    // FFN1 + relu -> h1 bf16 pair only
    hmma_gemm<1><<<dim3(FFN_DIM / 128, BN / 128), 512, SMEM_TOTAL>>>(
        pYh, pYl, pW1h, pW1l, b1, nullptr, pH1h, pH1l, FFN_DIM, H);
    // FFN2 -> ff fp32
    hmma_gemm<0><<<dim3(H / 128, BN / 128), 512, SMEM_TOTAL>>>(
        pH1h, pH1l, pW2h, pW2l, b2, pFf, nullptr, nullptr, H, FFN_DIM);
    // LN2 (+residual y, +mask) -> output
    ln_kernel<<<BN, 256>>>(pFf, pY, ln_g, ln_b, outp, nullptr, nullptr, masks, 1, 1);
    (void)in_sizes; (void)out_size;
}

// round 8
// speedup vs baseline: 5.3059x; 1.7607x over previous
#include <cuda_runtime.h>
#include <cuda_fp16.h>
#include <math.h>
#include <stdint.h>

#define BB 8
#define SS 512
#define NSPAN 512
#define H 768
#define NH 4
#define HD 192
#define FFN_DIM 3072
#define LSPAN 32
#define BS (BB*SS)      // 4096 token rows
#define BN (BB*NSPAN)   // 4096 span rows

// ---------------- scratch (static device globals; no allocations) ----------
__device__ __half g_X16[(size_t)BS*H];
__device__ __half g_kvw16[(size_t)2*H*H];
__device__ __half g_ow16[(size_t)H*H];
__device__ __half g_w116[(size_t)FFN_DIM*H];
__device__ __half g_w216[(size_t)H*FFN_DIM];
__device__ float  g_KV[(size_t)BS*2*H];   // K cols 0..767, V cols 768..1535
__device__ __half g_ctx16[(size_t)BN*H];
__device__ float  g_ao[(size_t)BN*H];
__device__ float  g_y[(size_t)BN*H];
__device__ __half g_y16[(size_t)BN*H];
__device__ __half g_h116[(size_t)BN*FFN_DIM];
__device__ float  g_ff[(size_t)BN*H];
__device__ float  g_qc[H];
__device__ float  g_bias2[H];             // out_b + dummy_query

// ---------------- PTX helpers ----------------------------------------------
__device__ __forceinline__ uint32_t smem_u32(const void* p) {
    uint32_t a;
    asm("{ .reg .u64 t; cvta.to.shared.u64 t, %1; cvt.u32.u64 %0, t; }" : "=r"(a) : "l"(p));
    return a;
}
#define LDSM4(r, addr) \
    asm volatile("ldmatrix.sync.aligned.m8n8.x4.shared.b16 {%0,%1,%2,%3}, [%4];" \
        : "=r"((r)[0]), "=r"((r)[1]), "=r"((r)[2]), "=r"((r)[3]) : "r"(addr))
#define MMA_F16(d, a, b0, b1) \
    asm volatile("mma.sync.aligned.m16n8k16.row.col.f32.f16.f16.f32 " \
        "{%0,%1,%2,%3}, {%4,%5,%6,%7}, {%8,%9}, {%0,%1,%2,%3};" \
        : "+f"((d)[0]), "+f"((d)[1]), "+f"((d)[2]), "+f"((d)[3]) \
        : "r"((a)[0]), "r"((a)[1]), "r"((a)[2]), "r"((a)[3]), "r"(b0), "r"(b1))
#define CP16(sdst, gsrc) \
    asm volatile("cp.async.cg.shared.global [%0], [%1], 16;" :: "r"(sdst), "l"(gsrc))
#define CP_COMMIT() asm volatile("cp.async.commit_group;" ::: "memory")
#define CP_WAIT1()  asm volatile("cp.async.wait_group 1;" ::: "memory")
#define CP_WAIT0()  asm volatile("cp.async.wait_group 0;" ::: "memory")

#define TSTRIDE 72                       // half elems per smem row (64 + 8 pad)
#define TILE_B (128*TSTRIDE*2)           // 18432 B per tile
#define SMEM_TOTAL (4*TILE_B + 512)      // 2 stages x 2 tiles + bias

// ---------------- HMMA GEMM: C[M,N] = A[M,K] @ W[N,K]^T + bias (fp16 in) ---
// Block 128x128, 512 thr (16 warps, 4Mx4N), warp 32x32. cp.async 2-stage.
// MODE 0: fp32 out. MODE 1: relu then fp16 out.
template<int MODE>
__global__ void __launch_bounds__(512, 1)
hmma_gemm(const __half* __restrict__ A, const __half* __restrict__ W,
          const float* __restrict__ bias, float* __restrict__ C,
          __half* __restrict__ Ch, int N, int K) {
    extern __shared__ char sm[];
    uint32_t sb = smem_u32(sm);
    float* sbias = (float*)(sm + 4 * TILE_B);
    int tid = threadIdx.x, wid = tid >> 5, lid = tid & 31;
    int m0 = blockIdx.y * 128, n0 = blockIdx.x * 128;
    int warp_m = wid >> 2, warp_n = wid & 3;     // 4 x 4
    int wm0 = warp_m * 32, wn0 = warp_n * 32;

    if (tid < 128) sbias[tid] = bias[n0 + tid];

    float acc[2][4][4];
    #pragma unroll
    for (int mt = 0; mt < 2; mt++)
        #pragma unroll
        for (int nt = 0; nt < 4; nt++)
            #pragma unroll
            for (int j = 0; j < 4; j++) acc[mt][nt][j] = 0.f;

    // loader coords: 512 threads cover 64 rows x 8 chunks; 2 iterations for 128 rows
    int lrow = tid >> 3, lc16 = tid & 7;

    uint32_t a_rel = (uint32_t)(((wm0 + (lid & 15)) * TSTRIDE + ((lid >> 4) << 3)) * 2);
    uint32_t w_rel = (uint32_t)(TILE_B + ((wn0 + (lid & 15)) * TSTRIDE + ((lid >> 4) << 3)) * 2);

    int nsteps = K / 64;

    auto load_chunk = [&](int s, int buf) {
        uint32_t base = sb + (uint32_t)buf * 2 * TILE_B;
        int k0 = s * 64;
        #pragma unroll
        for (int it = 0; it < 2; it++) {
            int row = lrow + it * 64;
            uint32_t so = (uint32_t)(row * TSTRIDE * 2 + lc16 * 16);
            const char* pa = (const char*)(A + (size_t)(m0 + row) * K + k0) + lc16 * 16;
            const char* pb = (const char*)(W + (size_t)(n0 + row) * K + k0) + lc16 * 16;
            CP16(base + 0 * TILE_B + so, pa);
            CP16(base + 1 * TILE_B + so, pb);
        }
    };

    load_chunk(0, 0);
    CP_COMMIT();

    for (int s = 0; s < nsteps; s++) {
        int buf = s & 1;
        if (s + 1 < nsteps) {
            load_chunk(s + 1, (s + 1) & 1);
            CP_COMMIT();
            CP_WAIT1();
        } else {
            CP_WAIT0();
        }
        __syncthreads();

        uint32_t a_off = sb + (uint32_t)buf * 2 * TILE_B + a_rel;
        uint32_t w_off = sb + (uint32_t)buf * 2 * TILE_B + w_rel;
        #pragma unroll
        for (int kk = 0; kk < 4; kk++) {
            uint32_t ah[2][4], bh[2][4];
            #pragma unroll
            for (int t = 0; t < 2; t++) {
                uint32_t off = (uint32_t)(t * 16 * TSTRIDE * 2 + kk * 32);
                LDSM4(ah[t], a_off + off);
                LDSM4(bh[t], w_off + off);
            }
            #pragma unroll
            for (int mt = 0; mt < 2; mt++)
                #pragma unroll
                for (int nt = 0; nt < 4; nt++) {
                    int g = nt >> 1, hh = nt & 1;
                    MMA_F16(acc[mt][nt], ah[mt], bh[g][hh], bh[g][2 + hh]);
                }
        }
        __syncthreads();
    }

    // ---- epilogue ----
    int g8 = lid >> 2, tig = lid & 3;
    #pragma unroll
    for (int mt = 0; mt < 2; mt++) {
        int r0 = m0 + wm0 + mt * 16 + g8;
        #pragma unroll
        for (int nt = 0; nt < 4; nt++) {
            int cl = wn0 + nt * 8 + tig * 2;
            int c  = n0 + cl;
            float b0 = sbias[cl], b1 = sbias[cl + 1];
            float v00 = acc[mt][nt][0] + b0, v01 = acc[mt][nt][1] + b1;
            float v10 = acc[mt][nt][2] + b0, v11 = acc[mt][nt][3] + b1;
            if (MODE == 0) {
                *reinterpret_cast<float2*>(&C[(size_t)r0 * N + c])       = make_float2(v00, v01);
                *reinterpret_cast<float2*>(&C[(size_t)(r0 + 8) * N + c]) = make_float2(v10, v11);
            } else {
                v00 = fmaxf(v00, 0.f); v01 = fmaxf(v01, 0.f);
                v10 = fmaxf(v10, 0.f); v11 = fmaxf(v11, 0.f);
                __half2* CH = (__half2*)Ch;
                CH[((size_t)r0 * N + c) >> 1]       = __floats2half2_rn(v00, v01);
                CH[((size_t)(r0 + 8) * N + c) >> 1] = __floats2half2_rn(v10, v11);
            }
        }
    }
}

// ---------------- fp32 -> fp16 ----------------------------------------------
__global__ void cvt_half(const float* __restrict__ s, __half* __restrict__ h, int n) {
    int i = blockIdx.x * 256 + threadIdx.x;
    if (i >= n) return;
    h[i] = __float2half_rn(s[i]);
}

// ---------------- X = token_reps + PE -> fp16 ------------------------------
__global__ void add_pe_kernel(const float* __restrict__ tok) {
    int idx = blockIdx.x * blockDim.x + threadIdx.x;
    if (idx >= BS * H) return;
    int d   = idx % H;
    int row = idx / H;
    int pos = row % SS;
    int i2  = d & ~1;
    const float c = (float)(-9.210340371976184 / (double)H);
    float freq = expf((float)i2 * c);
    float ang  = (float)pos * freq;
    float pe   = (d & 1) ? cosf(ang) : sinf(ang);
    g_X16[idx] = __float2half_rn(tok[idx] + pe);
}

// ---------------- q projection + fused bias --------------------------------
__global__ void proj_q_kernel(const float* __restrict__ dq,
                              const float* __restrict__ in_w,
                              const float* __restrict__ in_b,
                              const float* __restrict__ out_b) {
    int o = blockIdx.x * blockDim.x + threadIdx.x;
    if (o >= H) return;
    const float* wr = in_w + (size_t)o * H;
    float acc = in_b[o];
    #pragma unroll 4
    for (int c = 0; c < H; c++) acc += dq[c] * wr[c];
    g_qc[o]    = acc;
    g_bias2[o] = out_b[o] + dq[o];
}

// ---------------- attention: 1 block per span, warp per head ---------------
__global__ void attn_kernel(const int* __restrict__ span_ids,
                            const int* __restrict__ masks) {
    int span = blockIdx.x;
    int b    = span / NSPAN;
    __shared__ float sq[H];
    __shared__ float sattn[NH][LSPAN];
    __shared__ int sh_start, sh_len;

    int tid = threadIdx.x;           // 128
    if (tid == 0) {
        int st = span_ids[span * 2 + 0];
        int en = span_ids[span * 2 + 1];
        int mk = masks[span] ? 1 : 0;
        sh_start = st;
        sh_len   = (en - st) * mk;
    }
    for (int i = tid; i < H; i += 128) sq[i] = g_qc[i];
    __syncthreads();

    int start = sh_start, len = sh_len;
    int h = tid >> 5;
    int l = tid & 31;

    const float scale = 1.0f / sqrtf((float)HD);
    float score = -INFINITY;
    if (l < len) {
        const float* kr = g_KV + ((size_t)(b * SS + start + l)) * (2 * H) + h * HD;
        const float* qh = sq + h * HD;
        float acc = 0.f;
        #pragma unroll
        for (int d = 0; d < HD; d += 4) {
            float4 k4 = *reinterpret_cast<const float4*>(kr + d);
            acc += qh[d] * k4.x + qh[d + 1] * k4.y + qh[d + 2] * k4.z + qh[d + 3] * k4.w;
        }
        score = acc * scale;
    }
    float mx = score;
    #pragma unroll
    for (int o = 16; o > 0; o >>= 1) mx = fmaxf(mx, __shfl_xor_sync(0xffffffffu, mx, o));
    float e = (l < len) ? expf(score - mx) : 0.f;
    float sum = e;
    #pragma unroll
    for (int o = 16; o > 0; o >>= 1) sum += __shfl_xor_sync(0xffffffffu, sum, o);
    sattn[h][l] = (sum > 0.f) ? (e / sum) : 0.f;
    __syncthreads();

    const float* rowbase = g_KV + ((size_t)(b * SS + start)) * (2 * H) + H;
    for (int o = tid; o < H; o += 128) {
        int hh = o / HD;
        float acc = 0.f;
        const float* vp = rowbase + o;
        for (int l2 = 0; l2 < len; l2++)
            acc += sattn[hh][l2] * vp[(size_t)l2 * 2 * H];
        g_ctx16[(size_t)span * H + o] = __float2half_rn(acc);
    }
}

// ---------------- LayerNorm; optional residual + mask + fp16 out -----------
__global__ void ln_kernel(const float* __restrict__ in, const float* __restrict__ res,
                          const float* __restrict__ gam, const float* __restrict__ bet,
                          float* __restrict__ out, __half* __restrict__ oh,
                          const int* __restrict__ masks, int has_res, int mask_out) {
    int row = blockIdx.x;
    __shared__ float sv[H];
    __shared__ float red[8];
    int tid = threadIdx.x;           // 256

    float s = 0.f;
    for (int i = tid; i < H; i += 256) {
        float v = in[(size_t)row * H + i];
        if (has_res) v += res[(size_t)row * H + i];
        sv[i] = v;
        s += v;
    }
    #pragma unroll
    for (int o = 16; o > 0; o >>= 1) s += __shfl_xor_sync(0xffffffffu, s, o);
    if ((tid & 31) == 0) red[tid >> 5] = s;
    __syncthreads();
    float tot = 0.f;
    #pragma unroll
    for (int w = 0; w < 8; w++) tot += red[w];
    float mean = tot / (float)H;
    __syncthreads();

    float vs = 0.f;
    for (int i = tid; i < H; i += 256) {
        float d = sv[i] - mean;
        vs += d * d;
    }
    #pragma unroll
    for (int o = 16; o > 0; o >>= 1) vs += __shfl_xor_sync(0xffffffffu, vs, o);
    if ((tid & 31) == 0) red[tid >> 5] = vs;
    __syncthreads();
    float vtot = 0.f;
    #pragma unroll
    for (int w = 0; w < 8; w++) vtot += red[w];
    float rstd = rsqrtf(vtot / (float)H + 1e-5f);

    int keep = mask_out ? (masks[row] ? 1 : 0) : 1;
    for (int i = tid; i < H; i += 256) {
        float val = (sv[i] - mean) * rstd * gam[i] + bet[i];
        val = keep ? val : 0.f;
        out[(size_t)row * H + i] = val;
        if (oh) oh[(size_t)row * H + i] = __float2half_rn(val);
    }
}

// ---------------- launch ---------------------------------------------------
extern "C" void kernel_launch(void* const* d_in, const int* in_sizes, int n_in,
                              void* d_out, int out_size) {
    const float* tok   = (const float*)d_in[0];
    const int*   sids  = (const int*)d_in[1];
    const int*   masks = (const int*)d_in[2];    // bool -> int32 on the wire
    int base = (n_in >= 15) ? 4 : 3;
    const float* dq    = (const float*)d_in[base + 0];
    const float* in_w  = (const float*)d_in[base + 1];
    const float* in_b  = (const float*)d_in[base + 2];
    const float* out_w = (const float*)d_in[base + 3];
    const float* out_b = (const float*)d_in[base + 4];
    const float* ln_g  = (const float*)d_in[base + 5];
    const float* ln_b  = (const float*)d_in[base + 6];
    const float* w1    = (const float*)d_in[base + 7];
    const float* b1    = (const float*)d_in[base + 8];
    const float* w2    = (const float*)d_in[base + 9];
    const float* b2    = (const float*)d_in[base + 10];
    float* outp = (float*)d_out;

    float *pKV, *pAo, *pY, *pFf, *pBias2;
    __half *pX, *pKW, *pOW, *pW1, *pW2, *pCx, *pY16, *pH1;
    cudaGetSymbolAddress((void**)&pKV,   g_KV);
    cudaGetSymbolAddress((void**)&pAo,   g_ao);
    cudaGetSymbolAddress((void**)&pY,    g_y);
    cudaGetSymbolAddress((void**)&pFf,   g_ff);
    cudaGetSymbolAddress((void**)&pBias2,g_bias2);
    cudaGetSymbolAddress((void**)&pX,    g_X16);
    cudaGetSymbolAddress((void**)&pKW,   g_kvw16);
    cudaGetSymbolAddress((void**)&pOW,   g_ow16);
    cudaGetSymbolAddress((void**)&pW1,   g_w116);
    cudaGetSymbolAddress((void**)&pW2,   g_w216);
    cudaGetSymbolAddress((void**)&pCx,   g_ctx16);
    cudaGetSymbolAddress((void**)&pY16,  g_y16);
    cudaGetSymbolAddress((void**)&pH1,   g_h116);

    cudaFuncSetAttribute(hmma_gemm<0>, cudaFuncAttributeMaxDynamicSharedMemorySize, SMEM_TOTAL);
    cudaFuncSetAttribute(hmma_gemm<1>, cudaFuncAttributeMaxDynamicSharedMemorySize, SMEM_TOTAL);

    // launch order chosen so the 4th launch (ncu capture point) is the KV GEMM
    add_pe_kernel<<<(BS * H + 255) / 256, 256>>>(tok);                               // 1
    cvt_half<<<(2 * H * H + 255) / 256, 256>>>(in_w + (size_t)H * H, pKW, 2 * H * H);// 2
    proj_q_kernel<<<3, 256>>>(dq, in_w, in_b, out_b);                                // 3
    // KV projection: [4096, 1536] fp32                                              // 4 (profiled)
    hmma_gemm<0><<<dim3(1536 / 128, BS / 128), 512, SMEM_TOTAL>>>(
        pX, pKW, in_b + H, pKV, nullptr, 2 * H, H);
    // span attention -> ctx fp16
    attn_kernel<<<BN, 128>>>(sids, masks);
    cvt_half<<<(H * H + 255) / 256, 256>>>(out_w, pOW, H * H);
    // out projection (+out_b + dummy_query): fp32 ao
    hmma_gemm<0><<<dim3(H / 128, BN / 128), 512, SMEM_TOTAL>>>(
        pCx, pOW, pBias2, pAo, nullptr, H, H);
    // LN1 -> y fp32 + fp16
    ln_kernel<<<BN, 256>>>(pAo, nullptr, ln_g, ln_b, pY, pY16, nullptr, 0, 0);
    cvt_half<<<(FFN_DIM * H + 255) / 256, 256>>>(w1, pW1, FFN_DIM * H);
    // FFN1 + relu -> h1 fp16
    hmma_gemm<1><<<dim3(FFN_DIM / 128, BN / 128), 512, SMEM_TOTAL>>>(
        pY16, pW1, b1, nullptr, pH1, FFN_DIM, H);
    cvt_half<<<(H * FFN_DIM + 255) / 256, 256>>>(w2, pW2, H * FFN_DIM);
    // FFN2 -> ff fp32
    hmma_gemm<0><<<dim3(H / 128, BN / 128), 512, SMEM_TOTAL>>>(
        pH1, pW2, b2, pFf, nullptr, H, FFN_DIM);
    // LN2 (+residual y, +mask) -> output
    ln_kernel<<<BN, 256>>>(pFf, pY, ln_g, ln_b, outp, nullptr, masks, 1, 1);
    (void)in_sizes; (void)out_size;
}

// round 9
// speedup vs baseline: 5.6055x; 1.0565x over previous
#include <cuda_runtime.h>
#include <cuda_fp16.h>
#include <math.h>
#include <stdint.h>

#define BB 8
#define SS 512
#define NSPAN 512
#define H 768
#define NH 4
#define HD 192
#define FFN_DIM 3072
#define LSPAN 32
#define BS (BB*SS)      // 4096 token rows
#define BN (BB*NSPAN)   // 4096 span rows

// ---------------- scratch (static device globals; no allocations) ----------
__device__ __half g_X16[(size_t)BS*H];
__device__ __half g_kvw16[(size_t)2*H*H];
__device__ __half g_ow16[(size_t)H*H];
__device__ __half g_w116[(size_t)FFN_DIM*H];
__device__ __half g_w216[(size_t)H*FFN_DIM];
__device__ float  g_KV[(size_t)BS*2*H];   // K cols 0..767, V cols 768..1535
__device__ __half g_ctx16[(size_t)BN*H];
__device__ float  g_ao[(size_t)BN*H];
__device__ float  g_y[(size_t)BN*H];
__device__ __half g_y16[(size_t)BN*H];
__device__ __half g_h116[(size_t)BN*FFN_DIM];
__device__ float  g_ff[(size_t)BN*H];
__device__ float  g_qc[H];
__device__ float  g_bias2[H];             // out_b + dummy_query

// ---------------- PTX helpers ----------------------------------------------
__device__ __forceinline__ uint32_t smem_u32(const void* p) {
    uint32_t a;
    asm("{ .reg .u64 t; cvta.to.shared.u64 t, %1; cvt.u32.u64 %0, t; }" : "=r"(a) : "l"(p));
    return a;
}
#define LDSM4(r, addr) \
    asm volatile("ldmatrix.sync.aligned.m8n8.x4.shared.b16 {%0,%1,%2,%3}, [%4];" \
        : "=r"((r)[0]), "=r"((r)[1]), "=r"((r)[2]), "=r"((r)[3]) : "r"(addr))
#define MMA_F16(d, a, b0, b1) \
    asm volatile("mma.sync.aligned.m16n8k16.row.col.f32.f16.f16.f32 " \
        "{%0,%1,%2,%3}, {%4,%5,%6,%7}, {%8,%9}, {%0,%1,%2,%3};" \
        : "+f"((d)[0]), "+f"((d)[1]), "+f"((d)[2]), "+f"((d)[3]) \
        : "r"((a)[0]), "r"((a)[1]), "r"((a)[2]), "r"((a)[3]), "r"(b0), "r"(b1))
#define CP16(sdst, gsrc) \
    asm volatile("cp.async.cg.shared.global [%0], [%1], 16;" :: "r"(sdst), "l"(gsrc))
#define CP_COMMIT() asm volatile("cp.async.commit_group;" ::: "memory")
#define CP_WAIT1()  asm volatile("cp.async.wait_group 1;" ::: "memory")
#define CP_WAIT0()  asm volatile("cp.async.wait_group 0;" ::: "memory")

#define TSTRIDE 72                       // half elems per smem row (64 + 8 pad)
#define TILE_B (128*TSTRIDE*2)           // 18432 B per tile
#define SMEM_TOTAL (4*TILE_B + 512)      // 2 stages x 2 tiles + bias (74 KB)

// ---------------- HMMA GEMM: C[M,N] = A[M,K] @ W[N,K]^T + bias (fp16 in) ---
// Block 128x128, 256 thr (8 warps, 2Mx4N), warp 64x32. cp.async 2-stage.
// 2 CTAs/SM (launch_bounds(256,2)) for cross-CTA latency hiding.
// MODE 0: fp32 out. MODE 1: relu then fp16 out.
template<int MODE>
__global__ void __launch_bounds__(256, 2)
hmma_gemm(const __half* __restrict__ A, const __half* __restrict__ W,
          const float* __restrict__ bias, float* __restrict__ C,
          __half* __restrict__ Ch, int N, int K) {
    extern __shared__ char sm[];
    uint32_t sb = smem_u32(sm);
    float* sbias = (float*)(sm + 4 * TILE_B);
    int tid = threadIdx.x, wid = tid >> 5, lid = tid & 31;
    int m0 = blockIdx.y * 128, n0 = blockIdx.x * 128;
    int warp_m = wid >> 2, warp_n = wid & 3;     // 2 x 4
    int wm0 = warp_m * 64, wn0 = warp_n * 32;

    if (tid < 128) sbias[tid] = bias[n0 + tid];

    float acc[4][4][4];
    #pragma unroll
    for (int mt = 0; mt < 4; mt++)
        #pragma unroll
        for (int nt = 0; nt < 4; nt++)
            #pragma unroll
            for (int j = 0; j < 4; j++) acc[mt][nt][j] = 0.f;

    // loader coords: 256 threads cover 32 rows x 8 chunks; 4 iters for 128 rows
    int lrow = tid >> 3, lc16 = tid & 7;

    uint32_t a_rel = (uint32_t)(((wm0 + (lid & 15)) * TSTRIDE + ((lid >> 4) << 3)) * 2);
    uint32_t w_rel = (uint32_t)(TILE_B + ((wn0 + (lid & 15)) * TSTRIDE + ((lid >> 4) << 3)) * 2);

    int nsteps = K / 64;

    auto load_chunk = [&](int s, int buf) {
        uint32_t base = sb + (uint32_t)buf * 2 * TILE_B;
        int k0 = s * 64;
        #pragma unroll
        for (int it = 0; it < 4; it++) {
            int row = lrow + it * 32;
            uint32_t so = (uint32_t)(row * TSTRIDE * 2 + lc16 * 16);
            const char* pa = (const char*)(A + (size_t)(m0 + row) * K + k0) + lc16 * 16;
            const char* pb = (const char*)(W + (size_t)(n0 + row) * K + k0) + lc16 * 16;
            CP16(base + 0 * TILE_B + so, pa);
            CP16(base + 1 * TILE_B + so, pb);
        }
    };

    load_chunk(0, 0);
    CP_COMMIT();

    for (int s = 0; s < nsteps; s++) {
        int buf = s & 1;
        if (s + 1 < nsteps) {
            load_chunk(s + 1, (s + 1) & 1);
            CP_COMMIT();
            CP_WAIT1();
        } else {
            CP_WAIT0();
        }
        __syncthreads();

        uint32_t a_off = sb + (uint32_t)buf * 2 * TILE_B + a_rel;
        uint32_t w_off = sb + (uint32_t)buf * 2 * TILE_B + w_rel;
        #pragma unroll
        for (int kk = 0; kk < 4; kk++) {
            uint32_t ah[4][4], bh[2][4];
            #pragma unroll
            for (int t = 0; t < 4; t++) {
                uint32_t off = (uint32_t)(t * 16 * TSTRIDE * 2 + kk * 32);
                LDSM4(ah[t], a_off + off);
            }
            #pragma unroll
            for (int t = 0; t < 2; t++) {
                uint32_t off = (uint32_t)(t * 16 * TSTRIDE * 2 + kk * 32);
                LDSM4(bh[t], w_off + off);
            }
            #pragma unroll
            for (int mt = 0; mt < 4; mt++)
                #pragma unroll
                for (int nt = 0; nt < 4; nt++) {
                    int g = nt >> 1, hh = nt & 1;
                    MMA_F16(acc[mt][nt], ah[mt], bh[g][hh], bh[g][2 + hh]);
                }
        }
        __syncthreads();
    }

    // ---- epilogue ----
    int g8 = lid >> 2, tig = lid & 3;
    #pragma unroll
    for (int mt = 0; mt < 4; mt++) {
        int r0 = m0 + wm0 + mt * 16 + g8;
        #pragma unroll
        for (int nt = 0; nt < 4; nt++) {
            int cl = wn0 + nt * 8 + tig * 2;
            int c  = n0 + cl;
            float b0 = sbias[cl], b1 = sbias[cl + 1];
            float v00 = acc[mt][nt][0] + b0, v01 = acc[mt][nt][1] + b1;
            float v10 = acc[mt][nt][2] + b0, v11 = acc[mt][nt][3] + b1;
            if (MODE == 0) {
                *reinterpret_cast<float2*>(&C[(size_t)r0 * N + c])       = make_float2(v00, v01);
                *reinterpret_cast<float2*>(&C[(size_t)(r0 + 8) * N + c]) = make_float2(v10, v11);
            } else {
                v00 = fmaxf(v00, 0.f); v01 = fmaxf(v01, 0.f);
                v10 = fmaxf(v10, 0.f); v11 = fmaxf(v11, 0.f);
                __half2* CH = (__half2*)Ch;
                CH[((size_t)r0 * N + c) >> 1]       = __floats2half2_rn(v00, v01);
                CH[((size_t)(r0 + 8) * N + c) >> 1] = __floats2half2_rn(v10, v11);
            }
        }
    }
}

// ---------------- fp32 -> fp16 ----------------------------------------------
__global__ void cvt_half(const float* __restrict__ s, __half* __restrict__ h, int n) {
    int i = blockIdx.x * 256 + threadIdx.x;
    if (i >= n) return;
    h[i] = __float2half_rn(s[i]);
}

// ---------------- X = token_reps + PE -> fp16 ------------------------------
__global__ void add_pe_kernel(const float* __restrict__ tok) {
    int idx = blockIdx.x * blockDim.x + threadIdx.x;
    if (idx >= BS * H) return;
    int d   = idx % H;
    int row = idx / H;
    int pos = row % SS;
    int i2  = d & ~1;
    const float c = (float)(-9.210340371976184 / (double)H);
    float freq = expf((float)i2 * c);
    float ang  = (float)pos * freq;
    float pe   = (d & 1) ? cosf(ang) : sinf(ang);
    g_X16[idx] = __float2half_rn(tok[idx] + pe);
}

// ---------------- q projection + fused bias --------------------------------
__global__ void proj_q_kernel(const float* __restrict__ dq,
                              const float* __restrict__ in_w,
                              const float* __restrict__ in_b,
                              const float* __restrict__ out_b) {
    int o = blockIdx.x * blockDim.x + threadIdx.x;
    if (o >= H) return;
    const float* wr = in_w + (size_t)o * H;
    float acc = in_b[o];
    #pragma unroll 4
    for (int c = 0; c < H; c++) acc += dq[c] * wr[c];
    g_qc[o]    = acc;
    g_bias2[o] = out_b[o] + dq[o];
}

// ---------------- attention: 1 block per span, warp per head ---------------
__global__ void attn_kernel(const int* __restrict__ span_ids,
                            const int* __restrict__ masks) {
    int span = blockIdx.x;
    int b    = span / NSPAN;
    __shared__ float sq[H];
    __shared__ float sattn[NH][LSPAN];
    __shared__ int sh_start, sh_len;

    int tid = threadIdx.x;           // 128
    if (tid == 0) {
        int st = span_ids[span * 2 + 0];
        int en = span_ids[span * 2 + 1];
        int mk = masks[span] ? 1 : 0;
        sh_start = st;
        sh_len   = (en - st) * mk;
    }
    for (int i = tid; i < H; i += 128) sq[i] = g_qc[i];
    __syncthreads();

    int start = sh_start, len = sh_len;
    int h = tid >> 5;
    int l = tid & 31;

    const float scale = 1.0f / sqrtf((float)HD);
    float score = -INFINITY;
    if (l < len) {
        const float* kr = g_KV + ((size_t)(b * SS + start + l)) * (2 * H) + h * HD;
        const float* qh = sq + h * HD;
        float acc = 0.f;
        #pragma unroll
        for (int d = 0; d < HD; d += 4) {
            float4 k4 = *reinterpret_cast<const float4*>(kr + d);
            acc += qh[d] * k4.x + qh[d + 1] * k4.y + qh[d + 2] * k4.z + qh[d + 3] * k4.w;
        }
        score = acc * scale;
    }
    float mx = score;
    #pragma unroll
    for (int o = 16; o > 0; o >>= 1) mx = fmaxf(mx, __shfl_xor_sync(0xffffffffu, mx, o));
    float e = (l < len) ? expf(score - mx) : 0.f;
    float sum = e;
    #pragma unroll
    for (int o = 16; o > 0; o >>= 1) sum += __shfl_xor_sync(0xffffffffu, sum, o);
    sattn[h][l] = (sum > 0.f) ? (e / sum) : 0.f;
    __syncthreads();

    const float* rowbase = g_KV + ((size_t)(b * SS + start)) * (2 * H) + H;
    for (int o = tid; o < H; o += 128) {
        int hh = o / HD;
        float acc = 0.f;
        const float* vp = rowbase + o;
        for (int l2 = 0; l2 < len; l2++)
            acc += sattn[hh][l2] * vp[(size_t)l2 * 2 * H];
        g_ctx16[(size_t)span * H + o] = __float2half_rn(acc);
    }
}

// ---------------- LayerNorm; optional residual + mask + fp16 out -----------
__global__ void ln_kernel(const float* __restrict__ in, const float* __restrict__ res,
                          const float* __restrict__ gam, const float* __restrict__ bet,
                          float* __restrict__ out, __half* __restrict__ oh,
                          const int* __restrict__ masks, int has_res, int mask_out) {
    int row = blockIdx.x;
    __shared__ float sv[H];
    __shared__ float red[8];
    int tid = threadIdx.x;           // 256

    float s = 0.f;
    for (int i = tid; i < H; i += 256) {
        float v = in[(size_t)row * H + i];
        if (has_res) v += res[(size_t)row * H + i];
        sv[i] = v;
        s += v;
    }
    #pragma unroll
    for (int o = 16; o > 0; o >>= 1) s += __shfl_xor_sync(0xffffffffu, s, o);
    if ((tid & 31) == 0) red[tid >> 5] = s;
    __syncthreads();
    float tot = 0.f;
    #pragma unroll
    for (int w = 0; w < 8; w++) tot += red[w];
    float mean = tot / (float)H;
    __syncthreads();

    float vs = 0.f;
    for (int i = tid; i < H; i += 256) {
        float d = sv[i] - mean;
        vs += d * d;
    }
    #pragma unroll
    for (int o = 16; o > 0; o >>= 1) vs += __shfl_xor_sync(0xffffffffu, vs, o);
    if ((tid & 31) == 0) red[tid >> 5] = vs;
    __syncthreads();
    float vtot = 0.f;
    #pragma unroll
    for (int w = 0; w < 8; w++) vtot += red[w];
    float rstd = rsqrtf(vtot / (float)H + 1e-5f);

    int keep = mask_out ? (masks[row] ? 1 : 0) : 1;
    for (int i = tid; i < H; i += 256) {
        float val = (sv[i] - mean) * rstd * gam[i] + bet[i];
        val = keep ? val : 0.f;
        out[(size_t)row * H + i] = val;
        if (oh) oh[(size_t)row * H + i] = __float2half_rn(val);
    }
}

// ---------------- launch ---------------------------------------------------
extern "C" void kernel_launch(void* const* d_in, const int* in_sizes, int n_in,
                              void* d_out, int out_size) {
    const float* tok   = (const float*)d_in[0];
    const int*   sids  = (const int*)d_in[1];
    const int*   masks = (const int*)d_in[2];    // bool -> int32 on the wire
    int base = (n_in >= 15) ? 4 : 3;
    const float* dq    = (const float*)d_in[base + 0];
    const float* in_w  = (const float*)d_in[base + 1];
    const float* in_b  = (const float*)d_in[base + 2];
    const float* out_w = (const float*)d_in[base + 3];
    const float* out_b = (const float*)d_in[base + 4];
    const float* ln_g  = (const float*)d_in[base + 5];
    const float* ln_b  = (const float*)d_in[base + 6];
    const float* w1    = (const float*)d_in[base + 7];
    const float* b1    = (const float*)d_in[base + 8];
    const float* w2    = (const float*)d_in[base + 9];
    const float* b2    = (const float*)d_in[base + 10];
    float* outp = (float*)d_out;

    float *pKV, *pAo, *pY, *pFf, *pBias2;
    __half *pX, *pKW, *pOW, *pW1, *pW2, *pCx, *pY16, *pH1;
    cudaGetSymbolAddress((void**)&pKV,   g_KV);
    cudaGetSymbolAddress((void**)&pAo,   g_ao);
    cudaGetSymbolAddress((void**)&pY,    g_y);
    cudaGetSymbolAddress((void**)&pFf,   g_ff);
    cudaGetSymbolAddress((void**)&pBias2,g_bias2);
    cudaGetSymbolAddress((void**)&pX,    g_X16);
    cudaGetSymbolAddress((void**)&pKW,   g_kvw16);
    cudaGetSymbolAddress((void**)&pOW,   g_ow16);
    cudaGetSymbolAddress((void**)&pW1,   g_w116);
    cudaGetSymbolAddress((void**)&pW2,   g_w216);
    cudaGetSymbolAddress((void**)&pCx,   g_ctx16);
    cudaGetSymbolAddress((void**)&pY16,  g_y16);
    cudaGetSymbolAddress((void**)&pH1,   g_h116);

    cudaFuncSetAttribute(hmma_gemm<0>, cudaFuncAttributeMaxDynamicSharedMemorySize, SMEM_TOTAL);
    cudaFuncSetAttribute(hmma_gemm<1>, cudaFuncAttributeMaxDynamicSharedMemorySize, SMEM_TOTAL);

    // launch order chosen so the 4th launch (ncu capture point) is the KV GEMM
    add_pe_kernel<<<(BS * H + 255) / 256, 256>>>(tok);                               // 1
    cvt_half<<<(2 * H * H + 255) / 256, 256>>>(in_w + (size_t)H * H, pKW, 2 * H * H);// 2
    proj_q_kernel<<<3, 256>>>(dq, in_w, in_b, out_b);                                // 3
    // KV projection: [4096, 1536] fp32                                              // 4 (profiled)
    hmma_gemm<0><<<dim3(1536 / 128, BS / 128), 256, SMEM_TOTAL>>>(
        pX, pKW, in_b + H, pKV, nullptr, 2 * H, H);
    // span attention -> ctx fp16
    attn_kernel<<<BN, 128>>>(sids, masks);
    cvt_half<<<(H * H + 255) / 256, 256>>>(out_w, pOW, H * H);
    // out projection (+out_b + dummy_query): fp32 ao
    hmma_gemm<0><<<dim3(H / 128, BN / 128), 256, SMEM_TOTAL>>>(
        pCx, pOW, pBias2, pAo, nullptr, H, H);
    // LN1 -> y fp32 + fp16
    ln_kernel<<<BN, 256>>>(pAo, nullptr, ln_g, ln_b, pY, pY16, nullptr, 0, 0);
    cvt_half<<<(FFN_DIM * H + 255) / 256, 256>>>(w1, pW1, FFN_DIM * H);
    // FFN1 + relu -> h1 fp16
    hmma_gemm<1><<<dim3(FFN_DIM / 128, BN / 128), 256, SMEM_TOTAL>>>(
        pY16, pW1, b1, nullptr, pH1, FFN_DIM, H);
    cvt_half<<<(H * FFN_DIM + 255) / 256, 256>>>(w2, pW2, H * FFN_DIM);
    // FFN2 -> ff fp32
    hmma_gemm<0><<<dim3(H / 128, BN / 128), 256, SMEM_TOTAL>>>(
        pH1, pW2, b2, pFf, nullptr, H, FFN_DIM);
    // LN2 (+residual y, +mask) -> output
    ln_kernel<<<BN, 256>>>(pFf, pY, ln_g, ln_b, outp, nullptr, masks, 1, 1);
    (void)in_sizes; (void)out_size;
}